// round 1
// baseline (speedup 1.0000x reference)
#include <cuda_runtime.h>
#include <cstdint>

// Problem constants
#define B_    2
#define S_    2048
#define E_    2048
#define H_    32
#define KH_   8
#define HD_   64
#define F_    8192
#define KV_   (KH_*HD_)      // 512
#define QKVN  (E_ + 2*KV_)   // 3072
#define M_    (B_*S_)        // 4096

// -------- scratch (device globals: allocation-free) --------
__device__ float g_h   [(size_t)M_*E_];
__device__ float g_qkv [(size_t)M_*QKVN];
__device__ float g_q   [(size_t)B_*H_ *S_*HD_];
__device__ float g_k   [(size_t)B_*KH_*S_*HD_];
__device__ float g_v   [(size_t)B_*KH_*S_*HD_];
__device__ float g_o   [(size_t)M_*E_];
__device__ float g_h2  [(size_t)M_*E_];
__device__ float g_g   [(size_t)M_*E_];
__device__ float g_gate[(size_t)M_*F_];
__device__ float g_up  [(size_t)M_*F_];

// -------- packed f32x2 helpers (sm_103a FFMA2) --------
__device__ __forceinline__ unsigned long long pack2(float lo, float hi) {
    unsigned long long r;
    asm("mov.b64 %0, {%1, %2};" : "=l"(r) : "f"(lo), "f"(hi));
    return r;
}
__device__ __forceinline__ float2 unpack2(unsigned long long v) {
    float2 r;
    asm("mov.b64 {%0, %1}, %2;" : "=f"(r.x), "=f"(r.y) : "l"(v));
    return r;
}
__device__ __forceinline__ unsigned long long fma2(unsigned long long a,
                                                   unsigned long long b,
                                                   unsigned long long c) {
    unsigned long long d;
    asm("fma.rn.f32x2 %0, %1, %2, %3;" : "=l"(d) : "l"(a), "l"(b), "l"(c));
    return d;
}

// ============================================================
// RMSNorm: one block per row of 2048
// ============================================================
__global__ __launch_bounds__(256) void rmsnorm_kernel(
    const float* __restrict__ x, const float* __restrict__ w, float* __restrict__ o)
{
    const int tid = threadIdx.x;
    const size_t base = (size_t)blockIdx.x * E_;
    float4 v0 = *reinterpret_cast<const float4*>(x + base + tid*4);
    float4 v1 = *reinterpret_cast<const float4*>(x + base + 1024 + tid*4);
    float ss = v0.x*v0.x + v0.y*v0.y + v0.z*v0.z + v0.w*v0.w
             + v1.x*v1.x + v1.y*v1.y + v1.z*v1.z + v1.w*v1.w;
    #pragma unroll
    for (int off = 16; off; off >>= 1) ss += __shfl_xor_sync(0xffffffffu, ss, off);
    __shared__ float sred[8];
    if ((tid & 31) == 0) sred[tid >> 5] = ss;
    __syncthreads();
    float tot = 0.f;
    #pragma unroll
    for (int i = 0; i < 8; i++) tot += sred[i];
    float inv = rsqrtf(tot * (1.0f / (float)E_) + 1e-5f);
    float4 w0 = *reinterpret_cast<const float4*>(w + tid*4);
    float4 w1 = *reinterpret_cast<const float4*>(w + 1024 + tid*4);
    float4 o0 = make_float4(v0.x*inv*w0.x, v0.y*inv*w0.y, v0.z*inv*w0.z, v0.w*inv*w0.w);
    float4 o1 = make_float4(v1.x*inv*w1.x, v1.y*inv*w1.y, v1.z*inv*w1.z, v1.w*inv*w1.w);
    *reinterpret_cast<float4*>(o + base + tid*4)        = o0;
    *reinterpret_cast<float4*>(o + base + 1024 + tid*4) = o1;
}

// ============================================================
// SGEMM NT: C[M,N] = A[M,K] * B[N,K]^T (+ optional residual)
// 128x128x16 tiles, 256 thr, 8x8 micro-tile, FFMA2, dbl-buffered smem
// Requires: M%128==0, N%128==0, K%16==0
// ============================================================
template<bool RES>
__global__ __launch_bounds__(256, 2) void sgemm_nt(
    const float* __restrict__ A, const float* __restrict__ B,
    const float* __restrict__ Res, float* __restrict__ C,
    int M, int N, int K)
{
    __shared__ __align__(16) float As[2][16][128];
    __shared__ __align__(16) float Bs[2][16][128];

    const int tid = threadIdx.x;
    const int bm = blockIdx.y * 128;
    const int bn = blockIdx.x * 128;

    // loader coords: float4 id = tid (+256): row=id>>2, kcol=(id&3)*4
    const int lr0 = tid >> 2;
    const int lc0 = (tid & 3) * 4;
    const float* Ag = A + (size_t)(bm + lr0) * K + lc0;
    const float* Bg = B + (size_t)(bn + lr0) * K + lc0;
    const size_t rowskip = (size_t)64 * K;

    // compute coords
    const int r0 = (tid >> 4) * 4;
    const int c0 = (tid & 15) * 4;

    unsigned long long acc[4][8];
    #pragma unroll
    for (int i = 0; i < 4; i++)
        #pragma unroll
        for (int j = 0; j < 8; j++) acc[i][j] = 0ull;

    // preload tile 0
    {
        float4 a0 = *reinterpret_cast<const float4*>(Ag);
        float4 a1 = *reinterpret_cast<const float4*>(Ag + rowskip);
        float4 b0 = *reinterpret_cast<const float4*>(Bg);
        float4 b1 = *reinterpret_cast<const float4*>(Bg + rowskip);
        As[0][lc0+0][lr0] = a0.x; As[0][lc0+1][lr0] = a0.y;
        As[0][lc0+2][lr0] = a0.z; As[0][lc0+3][lr0] = a0.w;
        As[0][lc0+0][lr0+64] = a1.x; As[0][lc0+1][lr0+64] = a1.y;
        As[0][lc0+2][lr0+64] = a1.z; As[0][lc0+3][lr0+64] = a1.w;
        Bs[0][lc0+0][lr0] = b0.x; Bs[0][lc0+1][lr0] = b0.y;
        Bs[0][lc0+2][lr0] = b0.z; Bs[0][lc0+3][lr0] = b0.w;
        Bs[0][lc0+0][lr0+64] = b1.x; Bs[0][lc0+1][lr0+64] = b1.y;
        Bs[0][lc0+2][lr0+64] = b1.z; Bs[0][lc0+3][lr0+64] = b1.w;
    }
    __syncthreads();

    const int KT = K >> 4;
    for (int kt = 0; kt < KT; ++kt) {
        const int cur = kt & 1;
        float4 pa0, pa1, pb0, pb1;
        const bool pf = (kt + 1 < KT);
        if (pf) {
            const float* Ap = Ag + (size_t)(kt + 1) * 16;
            const float* Bp = Bg + (size_t)(kt + 1) * 16;
            pa0 = *reinterpret_cast<const float4*>(Ap);
            pa1 = *reinterpret_cast<const float4*>(Ap + rowskip);
            pb0 = *reinterpret_cast<const float4*>(Bp);
            pb1 = *reinterpret_cast<const float4*>(Bp + rowskip);
        }
        #pragma unroll
        for (int kk = 0; kk < 16; kk++) {
            ulonglong2 aA = *reinterpret_cast<const ulonglong2*>(&As[cur][kk][r0]);
            ulonglong2 aB = *reinterpret_cast<const ulonglong2*>(&As[cur][kk][r0 + 64]);
            float4 b0 = *reinterpret_cast<const float4*>(&Bs[cur][kk][c0]);
            float4 b1 = *reinterpret_cast<const float4*>(&Bs[cur][kk][c0 + 64]);
            unsigned long long ap[4] = { aA.x, aA.y, aB.x, aB.y };
            unsigned long long bp[8] = {
                pack2(b0.x, b0.x), pack2(b0.y, b0.y), pack2(b0.z, b0.z), pack2(b0.w, b0.w),
                pack2(b1.x, b1.x), pack2(b1.y, b1.y), pack2(b1.z, b1.z), pack2(b1.w, b1.w)
            };
            #pragma unroll
            for (int i = 0; i < 4; i++)
                #pragma unroll
                for (int j = 0; j < 8; j++)
                    acc[i][j] = fma2(ap[i], bp[j], acc[i][j]);
        }
        if (pf) {
            const int nxt = cur ^ 1;
            As[nxt][lc0+0][lr0] = pa0.x; As[nxt][lc0+1][lr0] = pa0.y;
            As[nxt][lc0+2][lr0] = pa0.z; As[nxt][lc0+3][lr0] = pa0.w;
            As[nxt][lc0+0][lr0+64] = pa1.x; As[nxt][lc0+1][lr0+64] = pa1.y;
            As[nxt][lc0+2][lr0+64] = pa1.z; As[nxt][lc0+3][lr0+64] = pa1.w;
            Bs[nxt][lc0+0][lr0] = pb0.x; Bs[nxt][lc0+1][lr0] = pb0.y;
            Bs[nxt][lc0+2][lr0] = pb0.z; Bs[nxt][lc0+3][lr0] = pb0.w;
            Bs[nxt][lc0+0][lr0+64] = pb1.x; Bs[nxt][lc0+1][lr0+64] = pb1.y;
            Bs[nxt][lc0+2][lr0+64] = pb1.z; Bs[nxt][lc0+3][lr0+64] = pb1.w;
            __syncthreads();
        }
    }

    // epilogue: acc[ip][j] covers row pair (lo,hi) x col j
    #pragma unroll
    for (int ip = 0; ip < 4; ip++) {
        const int rbase = bm + r0 + ((ip >> 1) * 64) + ((ip & 1) * 2);
        #pragma unroll
        for (int jg = 0; jg < 2; jg++) {
            const int col = bn + c0 + jg * 64;
            float2 u0 = unpack2(acc[ip][jg*4+0]);
            float2 u1 = unpack2(acc[ip][jg*4+1]);
            float2 u2 = unpack2(acc[ip][jg*4+2]);
            float2 u3 = unpack2(acc[ip][jg*4+3]);
            float4 olo = make_float4(u0.x, u1.x, u2.x, u3.x);
            float4 ohi = make_float4(u0.y, u1.y, u2.y, u3.y);
            if (RES) {
                float4 rlo = *reinterpret_cast<const float4*>(Res + (size_t)rbase     * N + col);
                float4 rhi = *reinterpret_cast<const float4*>(Res + (size_t)(rbase+1) * N + col);
                olo.x += rlo.x; olo.y += rlo.y; olo.z += rlo.z; olo.w += rlo.w;
                ohi.x += rhi.x; ohi.y += rhi.y; ohi.z += rhi.z; ohi.w += rhi.w;
            }
            *reinterpret_cast<float4*>(C + (size_t)rbase     * N + col) = olo;
            *reinterpret_cast<float4*>(C + (size_t)(rbase+1) * N + col) = ohi;
        }
    }
}

// ============================================================
// RoPE + head reshape. qkv [M_, 3072] -> q[B,H,S,HD], k/v[B,KH,S,HD]
// one thread per (even,odd) pair
// ============================================================
__global__ __launch_bounds__(256) void rope_reshape_kernel(
    const float* __restrict__ qkv, const float* __restrict__ fc,
    float* __restrict__ qr, float* __restrict__ kr, float* __restrict__ vr)
{
    const int gid = blockIdx.x * 256 + threadIdx.x;
    if (gid >= M_ * (QKVN/2)) return;
    const int row = gid / (QKVN/2);
    const int col = (gid - row * (QKVN/2)) * 2;
    const int b = row >> 11;          // S_=2048
    const int s = row & (S_-1);
    const float* src = qkv + (size_t)row * QKVN + col;
    const float x0 = src[0], x1 = src[1];

    if (col < E_) {                       // Q
        const int hh = col >> 6, d = col & 63;
        const float c = fc[s*64 + d], sn = fc[s*64 + d + 1];
        float* dst = qr + ((((size_t)b*H_ + hh) * S_ + s) << 6) + d;
        dst[0] = x0*c - x1*sn; dst[1] = x1*c + x0*sn;
    } else if (col < E_ + KV_) {          // K
        const int kc = col - E_;
        const int kh = kc >> 6, d = kc & 63;
        const float c = fc[s*64 + d], sn = fc[s*64 + d + 1];
        float* dst = kr + ((((size_t)b*KH_ + kh) * S_ + s) << 6) + d;
        dst[0] = x0*c - x1*sn; dst[1] = x1*c + x0*sn;
    } else {                              // V (copy)
        const int vc = col - E_ - KV_;
        const int kh = vc >> 6, d = vc & 63;
        float* dst = vr + ((((size_t)b*KH_ + kh) * S_ + s) << 6) + d;
        dst[0] = x0; dst[1] = x1;
    }
}

// ============================================================
// Flash attention fp32, causal, GQA 4:1. 64x64 tiles, 256 thr.
// Output directly in [B*S, H*HD] layout for the O-projection GEMM.
// ============================================================
__global__ __launch_bounds__(256) void attn_kernel(
    const float* __restrict__ qr, const float* __restrict__ kr,
    const float* __restrict__ vr, float* __restrict__ of)
{
    extern __shared__ float sm[];
    float* sQ = sm;                  // [64][68]
    float* sK = sm + 64*68;
    float* sV = sm + 2*64*68;
    float* sP = sm + 3*64*68;

    const int tid = threadIdx.x;
    const int qt = blockIdx.x, h = blockIdx.y, b = blockIdx.z;
    const int kvh = h >> 2;
    const float* Q = qr + (((size_t)(b*H_ + h)) * S_ + qt*64) * HD_;
    const float* K = kr + ((size_t)(b*KH_ + kvh)) * S_ * HD_;
    const float* V = vr + ((size_t)(b*KH_ + kvh)) * S_ * HD_;

    #pragma unroll
    for (int i = 0; i < 4; i++) {
        const int id = tid + i*256;
        const int r = id >> 4, c = (id & 15) * 4;
        *reinterpret_cast<float4*>(&sQ[r*68 + c]) =
            *reinterpret_cast<const float4*>(Q + r*64 + c);
    }
    const int tr = tid >> 4, tc = tid & 15;

    float m_i[4], l_i[4], acc[4][4];
    #pragma unroll
    for (int i = 0; i < 4; i++) {
        m_i[i] = -1e30f; l_i[i] = 0.f;
        acc[i][0] = acc[i][1] = acc[i][2] = acc[i][3] = 0.f;
    }

    for (int kt = 0; kt <= qt; ++kt) {
        __syncthreads();   // prior iter done reading sK/sV/sP
        #pragma unroll
        for (int i = 0; i < 4; i++) {
            const int id = tid + i*256;
            const int r = id >> 4, c = (id & 15) * 4;
            *reinterpret_cast<float4*>(&sK[r*68 + c]) =
                *reinterpret_cast<const float4*>(K + ((size_t)kt*64 + r)*64 + c);
            *reinterpret_cast<float4*>(&sV[r*68 + c]) =
                *reinterpret_cast<const float4*>(V + ((size_t)kt*64 + r)*64 + c);
        }
        __syncthreads();

        float s[4][4] = {{0.f,0.f,0.f,0.f},{0.f,0.f,0.f,0.f},{0.f,0.f,0.f,0.f},{0.f,0.f,0.f,0.f}};
        #pragma unroll
        for (int d = 0; d < 64; d += 4) {
            float4 a[4], bb[4];
            #pragma unroll
            for (int i = 0; i < 4; i++) a[i]  = *reinterpret_cast<const float4*>(&sQ[(tr*4+i)*68 + d]);
            #pragma unroll
            for (int j = 0; j < 4; j++) bb[j] = *reinterpret_cast<const float4*>(&sK[(tc*4+j)*68 + d]);
            #pragma unroll
            for (int i = 0; i < 4; i++)
                #pragma unroll
                for (int j = 0; j < 4; j++)
                    s[i][j] += a[i].x*bb[j].x + a[i].y*bb[j].y + a[i].z*bb[j].z + a[i].w*bb[j].w;
        }

        const bool diag = (kt == qt);
        #pragma unroll
        for (int i = 0; i < 4; i++) {
            float p[4];
            #pragma unroll
            for (int j = 0; j < 4; j++) {
                float val = s[i][j] * 0.125f;                  // 1/sqrt(64)
                if (diag && (tc*4 + j) > (tr*4 + i)) val = -1e30f;
                s[i][j] = val;
            }
            float mx = fmaxf(fmaxf(s[i][0], s[i][1]), fmaxf(s[i][2], s[i][3]));
            #pragma unroll
            for (int off = 8; off; off >>= 1) mx = fmaxf(mx, __shfl_xor_sync(0xffffffffu, mx, off));
            const float mn = fmaxf(m_i[i], mx);
            const float alpha = __expf(m_i[i] - mn);
            float ts = 0.f;
            #pragma unroll
            for (int j = 0; j < 4; j++) { p[j] = __expf(s[i][j] - mn); ts += p[j]; }
            #pragma unroll
            for (int off = 8; off; off >>= 1) ts += __shfl_xor_sync(0xffffffffu, ts, off);
            l_i[i] = l_i[i] * alpha + ts;
            m_i[i] = mn;
            acc[i][0] *= alpha; acc[i][1] *= alpha; acc[i][2] *= alpha; acc[i][3] *= alpha;
            *reinterpret_cast<float4*>(&sP[(tr*4+i)*68 + tc*4]) = make_float4(p[0], p[1], p[2], p[3]);
        }
        __syncthreads();

        #pragma unroll 4
        for (int k = 0; k < 64; k++) {
            const float4 vv = *reinterpret_cast<const float4*>(&sV[k*68 + tc*4]);
            #pragma unroll
            for (int i = 0; i < 4; i++) {
                const float pk = sP[(tr*4+i)*68 + k];
                acc[i][0] = fmaf(pk, vv.x, acc[i][0]);
                acc[i][1] = fmaf(pk, vv.y, acc[i][1]);
                acc[i][2] = fmaf(pk, vv.z, acc[i][2]);
                acc[i][3] = fmaf(pk, vv.w, acc[i][3]);
            }
        }
    }

    #pragma unroll
    for (int i = 0; i < 4; i++) {
        const float inv = 1.0f / l_i[i];
        const size_t row = (size_t)b * S_ + qt*64 + tr*4 + i;
        float4 o = make_float4(acc[i][0]*inv, acc[i][1]*inv, acc[i][2]*inv, acc[i][3]*inv);
        *reinterpret_cast<float4*>(of + row * E_ + h*64 + tc*4) = o;
    }
}

// ============================================================
// SwiGLU: gate = silu(gate) * up   (in place)
// ============================================================
__global__ __launch_bounds__(256) void silu_mul_kernel(
    float* __restrict__ gate, const float* __restrict__ up)
{
    const size_t i = ((size_t)blockIdx.x * 256 + threadIdx.x) * 4;
    float4 g = *reinterpret_cast<float4*>(gate + i);
    float4 u = *reinterpret_cast<const float4*>(up + i);
    g.x = g.x * u.x / (1.f + __expf(-g.x));
    g.y = g.y * u.y / (1.f + __expf(-g.y));
    g.z = g.z * u.z / (1.f + __expf(-g.z));
    g.w = g.w * u.w / (1.f + __expf(-g.w));
    *reinterpret_cast<float4*>(gate + i) = g;
}

// ============================================================
// launch
// ============================================================
extern "C" void kernel_launch(void* const* d_in, const int* in_sizes, int n_in,
                              void* d_out, int out_size)
{
    (void)in_sizes; (void)n_in; (void)out_size;
    const float* x     = (const float*)d_in[0];
    // d_in[1] = attention_mask (causal tril) — implicit in the flash kernel
    const float* fc    = (const float*)d_in[2];
    const float* w_qkv = (const float*)d_in[3];
    const float* w_o   = (const float*)d_in[4];
    const float* w1    = (const float*)d_in[5];
    const float* w2    = (const float*)d_in[6];
    const float* w3    = (const float*)d_in[7];
    const float* anw   = (const float*)d_in[8];
    const float* fnw   = (const float*)d_in[9];
    float* out = (float*)d_out;

    float *h, *qkv, *q, *k, *v, *o, *h2, *g, *gate, *up;
    cudaGetSymbolAddress((void**)&h,    g_h);
    cudaGetSymbolAddress((void**)&qkv,  g_qkv);
    cudaGetSymbolAddress((void**)&q,    g_q);
    cudaGetSymbolAddress((void**)&k,    g_k);
    cudaGetSymbolAddress((void**)&v,    g_v);
    cudaGetSymbolAddress((void**)&o,    g_o);
    cudaGetSymbolAddress((void**)&h2,   g_h2);
    cudaGetSymbolAddress((void**)&g,    g_g);
    cudaGetSymbolAddress((void**)&gate, g_gate);
    cudaGetSymbolAddress((void**)&up,   g_up);

    // 1. attn rmsnorm
    rmsnorm_kernel<<<M_, 256>>>(x, anw, h);
    // 2. qkv = h @ w_qkv^T
    sgemm_nt<false><<<dim3(QKVN/128, M_/128), 256>>>(h, w_qkv, nullptr, qkv, M_, QKVN, E_);
    // 3. rope + reshape
    rope_reshape_kernel<<<(M_*(QKVN/2))/256, 256>>>(qkv, fc, q, k, v);
    // 4. attention
    cudaFuncSetAttribute(attn_kernel, cudaFuncAttributeMaxDynamicSharedMemorySize, 4*64*68*4);
    attn_kernel<<<dim3(S_/64, H_, B_), 256, 4*64*68*4>>>(q, k, v, o);
    // 5. h2 = x + o @ w_o^T
    sgemm_nt<true><<<dim3(E_/128, M_/128), 256>>>(o, w_o, x, h2, M_, E_, E_);
    // 6. ffn rmsnorm
    rmsnorm_kernel<<<M_, 256>>>(h2, fnw, g);
    // 7. gate / up projections
    sgemm_nt<false><<<dim3(F_/128, M_/128), 256>>>(g, w1, nullptr, gate, M_, F_, E_);
    sgemm_nt<false><<<dim3(F_/128, M_/128), 256>>>(g, w3, nullptr, up,   M_, F_, E_);
    // 8. swiglu
    silu_mul_kernel<<<((size_t)M_*F_/4)/256, 256>>>(gate, up);
    // 9. out = h2 + act @ w2^T
    sgemm_nt<true><<<dim3(E_/128, M_/128), 256>>>(gate, w2, h2, out, M_, E_, F_);
}

// round 2
// speedup vs baseline: 1.9386x; 1.9386x over previous
#include <cuda_runtime.h>
#include <cstdint>

// Problem constants
#define B_    2
#define S_    2048
#define E_    2048
#define H_    32
#define KH_   8
#define HD_   64
#define F_    8192
#define KV_   (KH_*HD_)      // 512
#define QKVN  (E_ + 2*KV_)   // 3072
#define M_    (B_*S_)        // 4096

// -------- scratch (device globals: allocation-free) --------
__device__ float g_h   [(size_t)M_*E_];
__device__ float g_qkv [(size_t)M_*QKVN];
__device__ float g_q   [(size_t)B_*H_ *S_*HD_];
__device__ float g_k   [(size_t)B_*KH_*S_*HD_];
__device__ float g_v   [(size_t)B_*KH_*S_*HD_];
__device__ float g_o   [(size_t)M_*E_];
__device__ float g_h2  [(size_t)M_*E_];
__device__ float g_g   [(size_t)M_*E_];
__device__ float g_gate[(size_t)M_*F_];
__device__ float g_up  [(size_t)M_*F_];

// ============================================================
// RMSNorm: one block per row of 2048
// ============================================================
__global__ __launch_bounds__(256) void rmsnorm_kernel(
    const float* __restrict__ x, const float* __restrict__ w, float* __restrict__ o)
{
    const int tid = threadIdx.x;
    const size_t base = (size_t)blockIdx.x * E_;
    float4 v0 = *reinterpret_cast<const float4*>(x + base + tid*4);
    float4 v1 = *reinterpret_cast<const float4*>(x + base + 1024 + tid*4);
    float ss = v0.x*v0.x + v0.y*v0.y + v0.z*v0.z + v0.w*v0.w
             + v1.x*v1.x + v1.y*v1.y + v1.z*v1.z + v1.w*v1.w;
    #pragma unroll
    for (int off = 16; off; off >>= 1) ss += __shfl_xor_sync(0xffffffffu, ss, off);
    __shared__ float sred[8];
    if ((tid & 31) == 0) sred[tid >> 5] = ss;
    __syncthreads();
    float tot = 0.f;
    #pragma unroll
    for (int i = 0; i < 8; i++) tot += sred[i];
    float inv = rsqrtf(tot * (1.0f / (float)E_) + 1e-5f);
    float4 w0 = *reinterpret_cast<const float4*>(w + tid*4);
    float4 w1 = *reinterpret_cast<const float4*>(w + 1024 + tid*4);
    float4 o0 = make_float4(v0.x*inv*w0.x, v0.y*inv*w0.y, v0.z*inv*w0.z, v0.w*inv*w0.w);
    float4 o1 = make_float4(v1.x*inv*w1.x, v1.y*inv*w1.y, v1.z*inv*w1.z, v1.w*inv*w1.w);
    *reinterpret_cast<float4*>(o + base + tid*4)        = o0;
    *reinterpret_cast<float4*>(o + base + 1024 + tid*4) = o1;
}

// -------- tf32 helpers --------
__device__ __forceinline__ float tf32_round(float x) {
    unsigned u;
    asm("cvt.rna.tf32.f32 %0, %1;" : "=r"(u) : "f"(x));
    return __uint_as_float(u);
}
__device__ __forceinline__ float4 tf32_round4(float4 v) {
    return make_float4(tf32_round(v.x), tf32_round(v.y), tf32_round(v.z), tf32_round(v.w));
}
__device__ __forceinline__ void mma_tf32(float* c,
    unsigned a0, unsigned a1, unsigned a2, unsigned a3,
    unsigned b0, unsigned b1)
{
    asm volatile(
        "mma.sync.aligned.m16n8k8.row.col.f32.tf32.tf32.f32 "
        "{%0,%1,%2,%3}, {%4,%5,%6,%7}, {%8,%9}, {%0,%1,%2,%3};"
        : "+f"(c[0]), "+f"(c[1]), "+f"(c[2]), "+f"(c[3])
        : "r"(a0), "r"(a1), "r"(a2), "r"(a3), "r"(b0), "r"(b1));
}

// ============================================================
// TF32 tensor-core GEMM NT: C[M,N] = A[M,K]*B[N,K]^T (+res)
// Block 128x128, K-tile 16, 256 thr (8 warps, 4x2), warp 32x64.
// Double-buffered smem, pitch 20 (conflict-free for frag loads).
// Requires M%128==0, N%128==0, K%16==0.
// ============================================================
template<bool RES>
__global__ __launch_bounds__(256, 2) void tf32gemm_nt(
    const float* __restrict__ A, const float* __restrict__ B,
    const float* __restrict__ Res, float* __restrict__ C,
    int M, int N, int K)
{
    __shared__ __align__(16) float As[2][128][20];
    __shared__ __align__(16) float Bs[2][128][20];

    const int tid  = threadIdx.x;
    const int lane = tid & 31;
    const int warp = tid >> 5;
    const int bm = blockIdx.y * 128;
    const int bn = blockIdx.x * 128;

    // warp tile origin: 4 warps along M (32 each), 2 along N (64 each)
    const int m0 = (warp & 3) * 32;
    const int n0 = (warp >> 2) * 64;

    // loader: 128x16 floats = 512 float4; 256 thr x 2
    const int lrow = tid >> 2;          // 0..63
    const int lcol = (tid & 3) * 4;     // 0,4,8,12
    const float* Ag = A + (size_t)(bm + lrow) * K + lcol;
    const float* Bg = B + (size_t)(bn + lrow) * K + lcol;
    const size_t rowskip = (size_t)64 * K;

    float acc[2][8][4];
    #pragma unroll
    for (int i = 0; i < 2; i++)
        #pragma unroll
        for (int j = 0; j < 8; j++)
            acc[i][j][0] = acc[i][j][1] = acc[i][j][2] = acc[i][j][3] = 0.f;

    // preload k-tile 0
    {
        float4 a0 = *reinterpret_cast<const float4*>(Ag);
        float4 a1 = *reinterpret_cast<const float4*>(Ag + rowskip);
        float4 b0 = *reinterpret_cast<const float4*>(Bg);
        float4 b1 = *reinterpret_cast<const float4*>(Bg + rowskip);
        *reinterpret_cast<float4*>(&As[0][lrow     ][lcol]) = tf32_round4(a0);
        *reinterpret_cast<float4*>(&As[0][lrow + 64][lcol]) = tf32_round4(a1);
        *reinterpret_cast<float4*>(&Bs[0][lrow     ][lcol]) = tf32_round4(b0);
        *reinterpret_cast<float4*>(&Bs[0][lrow + 64][lcol]) = tf32_round4(b1);
    }
    __syncthreads();

    const int gr = lane >> 2;   // 0..7
    const int gk = lane & 3;    // 0..3
    const int KT = K >> 4;

    for (int kt = 0; kt < KT; ++kt) {
        const int buf = kt & 1;
        const bool pf = (kt + 1 < KT);
        float4 pa0, pa1, pb0, pb1;
        if (pf) {
            const float* Ap = Ag + (size_t)(kt + 1) * 16;
            const float* Bp = Bg + (size_t)(kt + 1) * 16;
            pa0 = *reinterpret_cast<const float4*>(Ap);
            pa1 = *reinterpret_cast<const float4*>(Ap + rowskip);
            pb0 = *reinterpret_cast<const float4*>(Bp);
            pb1 = *reinterpret_cast<const float4*>(Bp + rowskip);
        }

        #pragma unroll
        for (int kk = 0; kk < 2; ++kk) {
            const int k0 = kk * 8 + gk;
            unsigned af[2][4];
            #pragma unroll
            for (int mi = 0; mi < 2; mi++) {
                const int r = m0 + mi * 16 + gr;
                af[mi][0] = __float_as_uint(As[buf][r    ][k0    ]);
                af[mi][1] = __float_as_uint(As[buf][r + 8][k0    ]);
                af[mi][2] = __float_as_uint(As[buf][r    ][k0 + 4]);
                af[mi][3] = __float_as_uint(As[buf][r + 8][k0 + 4]);
            }
            unsigned bfr[8][2];
            #pragma unroll
            for (int ni = 0; ni < 8; ni++) {
                const int r = n0 + ni * 8 + gr;
                bfr[ni][0] = __float_as_uint(Bs[buf][r][k0    ]);
                bfr[ni][1] = __float_as_uint(Bs[buf][r][k0 + 4]);
            }
            #pragma unroll
            for (int mi = 0; mi < 2; mi++)
                #pragma unroll
                for (int ni = 0; ni < 8; ni++)
                    mma_tf32(acc[mi][ni], af[mi][0], af[mi][1], af[mi][2], af[mi][3],
                             bfr[ni][0], bfr[ni][1]);
        }

        if (pf) {
            const int nxt = buf ^ 1;
            *reinterpret_cast<float4*>(&As[nxt][lrow     ][lcol]) = tf32_round4(pa0);
            *reinterpret_cast<float4*>(&As[nxt][lrow + 64][lcol]) = tf32_round4(pa1);
            *reinterpret_cast<float4*>(&Bs[nxt][lrow     ][lcol]) = tf32_round4(pb0);
            *reinterpret_cast<float4*>(&Bs[nxt][lrow + 64][lcol]) = tf32_round4(pb1);
            __syncthreads();
        }
    }

    // epilogue
    const int gc = (lane & 3) * 2;
    #pragma unroll
    for (int mi = 0; mi < 2; mi++) {
        #pragma unroll
        for (int ni = 0; ni < 8; ni++) {
            const int r = bm + m0 + mi * 16 + gr;
            const int c = bn + n0 + ni * 8 + gc;
            float2 lo = make_float2(acc[mi][ni][0], acc[mi][ni][1]);
            float2 hi = make_float2(acc[mi][ni][2], acc[mi][ni][3]);
            if (RES) {
                float2 rlo = *reinterpret_cast<const float2*>(Res + (size_t)r * N + c);
                float2 rhi = *reinterpret_cast<const float2*>(Res + (size_t)(r + 8) * N + c);
                lo.x += rlo.x; lo.y += rlo.y;
                hi.x += rhi.x; hi.y += rhi.y;
            }
            *reinterpret_cast<float2*>(C + (size_t)r * N + c)       = lo;
            *reinterpret_cast<float2*>(C + (size_t)(r + 8) * N + c) = hi;
        }
    }
}

// ============================================================
// RoPE + head reshape. qkv [M_, 3072] -> q[B,H,S,HD], k/v[B,KH,S,HD]
// ============================================================
__global__ __launch_bounds__(256) void rope_reshape_kernel(
    const float* __restrict__ qkv, const float* __restrict__ fc,
    float* __restrict__ qr, float* __restrict__ kr, float* __restrict__ vr)
{
    const int gid = blockIdx.x * 256 + threadIdx.x;
    if (gid >= M_ * (QKVN/2)) return;
    const int row = gid / (QKVN/2);
    const int col = (gid - row * (QKVN/2)) * 2;
    const int b = row >> 11;          // S_=2048
    const int s = row & (S_-1);
    const float* src = qkv + (size_t)row * QKVN + col;
    const float x0 = src[0], x1 = src[1];

    if (col < E_) {                       // Q
        const int hh = col >> 6, d = col & 63;
        const float c = fc[s*64 + d], sn = fc[s*64 + d + 1];
        float* dst = qr + ((((size_t)b*H_ + hh) * S_ + s) << 6) + d;
        dst[0] = x0*c - x1*sn; dst[1] = x1*c + x0*sn;
    } else if (col < E_ + KV_) {          // K
        const int kc = col - E_;
        const int kh = kc >> 6, d = kc & 63;
        const float c = fc[s*64 + d], sn = fc[s*64 + d + 1];
        float* dst = kr + ((((size_t)b*KH_ + kh) * S_ + s) << 6) + d;
        dst[0] = x0*c - x1*sn; dst[1] = x1*c + x0*sn;
    } else {                              // V (copy)
        const int vc = col - E_ - KV_;
        const int kh = vc >> 6, d = vc & 63;
        float* dst = vr + ((((size_t)b*KH_ + kh) * S_ + s) << 6) + d;
        dst[0] = x0; dst[1] = x1;
    }
}

// ============================================================
// Flash attention fp32, causal, GQA 4:1. 64x64 tiles, 256 thr.
// ============================================================
__global__ __launch_bounds__(256) void attn_kernel(
    const float* __restrict__ qr, const float* __restrict__ kr,
    const float* __restrict__ vr, float* __restrict__ of)
{
    extern __shared__ float sm[];
    float* sQ = sm;                  // [64][68]
    float* sK = sm + 64*68;
    float* sV = sm + 2*64*68;
    float* sP = sm + 3*64*68;

    const int tid = threadIdx.x;
    const int qt = blockIdx.x, h = blockIdx.y, b = blockIdx.z;
    const int kvh = h >> 2;
    const float* Q = qr + (((size_t)(b*H_ + h)) * S_ + qt*64) * HD_;
    const float* K = kr + ((size_t)(b*KH_ + kvh)) * S_ * HD_;
    const float* V = vr + ((size_t)(b*KH_ + kvh)) * S_ * HD_;

    #pragma unroll
    for (int i = 0; i < 4; i++) {
        const int id = tid + i*256;
        const int r = id >> 4, c = (id & 15) * 4;
        *reinterpret_cast<float4*>(&sQ[r*68 + c]) =
            *reinterpret_cast<const float4*>(Q + r*64 + c);
    }
    const int tr = tid >> 4, tc = tid & 15;

    float m_i[4], l_i[4], acc[4][4];
    #pragma unroll
    for (int i = 0; i < 4; i++) {
        m_i[i] = -1e30f; l_i[i] = 0.f;
        acc[i][0] = acc[i][1] = acc[i][2] = acc[i][3] = 0.f;
    }

    for (int kt = 0; kt <= qt; ++kt) {
        __syncthreads();
        #pragma unroll
        for (int i = 0; i < 4; i++) {
            const int id = tid + i*256;
            const int r = id >> 4, c = (id & 15) * 4;
            *reinterpret_cast<float4*>(&sK[r*68 + c]) =
                *reinterpret_cast<const float4*>(K + ((size_t)kt*64 + r)*64 + c);
            *reinterpret_cast<float4*>(&sV[r*68 + c]) =
                *reinterpret_cast<const float4*>(V + ((size_t)kt*64 + r)*64 + c);
        }
        __syncthreads();

        float s[4][4] = {{0.f,0.f,0.f,0.f},{0.f,0.f,0.f,0.f},{0.f,0.f,0.f,0.f},{0.f,0.f,0.f,0.f}};
        #pragma unroll
        for (int d = 0; d < 64; d += 4) {
            float4 a[4], bb[4];
            #pragma unroll
            for (int i = 0; i < 4; i++) a[i]  = *reinterpret_cast<const float4*>(&sQ[(tr*4+i)*68 + d]);
            #pragma unroll
            for (int j = 0; j < 4; j++) bb[j] = *reinterpret_cast<const float4*>(&sK[(tc*4+j)*68 + d]);
            #pragma unroll
            for (int i = 0; i < 4; i++)
                #pragma unroll
                for (int j = 0; j < 4; j++)
                    s[i][j] += a[i].x*bb[j].x + a[i].y*bb[j].y + a[i].z*bb[j].z + a[i].w*bb[j].w;
        }

        const bool diag = (kt == qt);
        #pragma unroll
        for (int i = 0; i < 4; i++) {
            float p[4];
            #pragma unroll
            for (int j = 0; j < 4; j++) {
                float val = s[i][j] * 0.125f;
                if (diag && (tc*4 + j) > (tr*4 + i)) val = -1e30f;
                s[i][j] = val;
            }
            float mx = fmaxf(fmaxf(s[i][0], s[i][1]), fmaxf(s[i][2], s[i][3]));
            #pragma unroll
            for (int off = 8; off; off >>= 1) mx = fmaxf(mx, __shfl_xor_sync(0xffffffffu, mx, off));
            const float mn = fmaxf(m_i[i], mx);
            const float alpha = __expf(m_i[i] - mn);
            float ts = 0.f;
            #pragma unroll
            for (int j = 0; j < 4; j++) { p[j] = __expf(s[i][j] - mn); ts += p[j]; }
            #pragma unroll
            for (int off = 8; off; off >>= 1) ts += __shfl_xor_sync(0xffffffffu, ts, off);
            l_i[i] = l_i[i] * alpha + ts;
            m_i[i] = mn;
            acc[i][0] *= alpha; acc[i][1] *= alpha; acc[i][2] *= alpha; acc[i][3] *= alpha;
            *reinterpret_cast<float4*>(&sP[(tr*4+i)*68 + tc*4]) = make_float4(p[0], p[1], p[2], p[3]);
        }
        __syncthreads();

        #pragma unroll 4
        for (int k = 0; k < 64; k++) {
            const float4 vv = *reinterpret_cast<const float4*>(&sV[k*68 + tc*4]);
            #pragma unroll
            for (int i = 0; i < 4; i++) {
                const float pk = sP[(tr*4+i)*68 + k];
                acc[i][0] = fmaf(pk, vv.x, acc[i][0]);
                acc[i][1] = fmaf(pk, vv.y, acc[i][1]);
                acc[i][2] = fmaf(pk, vv.z, acc[i][2]);
                acc[i][3] = fmaf(pk, vv.w, acc[i][3]);
            }
        }
    }

    #pragma unroll
    for (int i = 0; i < 4; i++) {
        const float inv = 1.0f / l_i[i];
        const size_t row = (size_t)b * S_ + qt*64 + tr*4 + i;
        float4 o = make_float4(acc[i][0]*inv, acc[i][1]*inv, acc[i][2]*inv, acc[i][3]*inv);
        *reinterpret_cast<float4*>(of + row * E_ + h*64 + tc*4) = o;
    }
}

// ============================================================
// SwiGLU: gate = silu(gate) * up   (in place)
// ============================================================
__global__ __launch_bounds__(256) void silu_mul_kernel(
    float* __restrict__ gate, const float* __restrict__ up)
{
    const size_t i = ((size_t)blockIdx.x * 256 + threadIdx.x) * 4;
    float4 g = *reinterpret_cast<float4*>(gate + i);
    float4 u = *reinterpret_cast<const float4*>(up + i);
    g.x = g.x * u.x / (1.f + __expf(-g.x));
    g.y = g.y * u.y / (1.f + __expf(-g.y));
    g.z = g.z * u.z / (1.f + __expf(-g.z));
    g.w = g.w * u.w / (1.f + __expf(-g.w));
    *reinterpret_cast<float4*>(gate + i) = g;
}

// ============================================================
// launch
// ============================================================
extern "C" void kernel_launch(void* const* d_in, const int* in_sizes, int n_in,
                              void* d_out, int out_size)
{
    (void)in_sizes; (void)n_in; (void)out_size;
    const float* x     = (const float*)d_in[0];
    const float* fc    = (const float*)d_in[2];
    const float* w_qkv = (const float*)d_in[3];
    const float* w_o   = (const float*)d_in[4];
    const float* w1    = (const float*)d_in[5];
    const float* w2    = (const float*)d_in[6];
    const float* w3    = (const float*)d_in[7];
    const float* anw   = (const float*)d_in[8];
    const float* fnw   = (const float*)d_in[9];
    float* out = (float*)d_out;

    float *h, *qkv, *q, *k, *v, *o, *h2, *g, *gate, *up;
    cudaGetSymbolAddress((void**)&h,    g_h);
    cudaGetSymbolAddress((void**)&qkv,  g_qkv);
    cudaGetSymbolAddress((void**)&q,    g_q);
    cudaGetSymbolAddress((void**)&k,    g_k);
    cudaGetSymbolAddress((void**)&v,    g_v);
    cudaGetSymbolAddress((void**)&o,    g_o);
    cudaGetSymbolAddress((void**)&h2,   g_h2);
    cudaGetSymbolAddress((void**)&g,    g_g);
    cudaGetSymbolAddress((void**)&gate, g_gate);
    cudaGetSymbolAddress((void**)&up,   g_up);

    // 1. attn rmsnorm
    rmsnorm_kernel<<<M_, 256>>>(x, anw, h);
    // 2. qkv = h @ w_qkv^T
    tf32gemm_nt<false><<<dim3(QKVN/128, M_/128), 256>>>(h, w_qkv, nullptr, qkv, M_, QKVN, E_);
    // 3. rope + reshape
    rope_reshape_kernel<<<(M_*(QKVN/2))/256, 256>>>(qkv, fc, q, k, v);
    // 4. attention
    cudaFuncSetAttribute(attn_kernel, cudaFuncAttributeMaxDynamicSharedMemorySize, 4*64*68*4);
    attn_kernel<<<dim3(S_/64, H_, B_), 256, 4*64*68*4>>>(q, k, v, o);
    // 5. h2 = x + o @ w_o^T
    tf32gemm_nt<true><<<dim3(E_/128, M_/128), 256>>>(o, w_o, x, h2, M_, E_, E_);
    // 6. ffn rmsnorm
    rmsnorm_kernel<<<M_, 256>>>(h2, fnw, g);
    // 7. gate / up projections
    tf32gemm_nt<false><<<dim3(F_/128, M_/128), 256>>>(g, w1, nullptr, gate, M_, F_, E_);
    tf32gemm_nt<false><<<dim3(F_/128, M_/128), 256>>>(g, w3, nullptr, up,   M_, F_, E_);
    // 8. swiglu
    silu_mul_kernel<<<((size_t)M_*F_/4)/256, 256>>>(gate, up);
    // 9. out = h2 + act @ w2^T
    tf32gemm_nt<true><<<dim3(E_/128, M_/128), 256>>>(gate, w2, h2, out, M_, E_, F_);
}

// round 4
// speedup vs baseline: 2.7314x; 1.4089x over previous
#include <cuda_runtime.h>
#include <cuda_fp16.h>
#include <cstdint>

// Problem constants
#define B_    2
#define S_    2048
#define E_    2048
#define H_    32
#define KH_   8
#define HD_   64
#define F_    8192
#define KV_   (KH_*HD_)      // 512
#define QKVN  (E_ + 2*KV_)   // 3072
#define M_    (B_*S_)        // 4096

// -------- scratch (device globals: allocation-free) --------
__device__ float g_h   [(size_t)M_*E_];
__device__ float g_qkv [(size_t)M_*QKVN];
__device__ float g_q   [(size_t)B_*H_ *S_*HD_];
__device__ float g_k   [(size_t)B_*KH_*S_*HD_];
__device__ float g_v   [(size_t)B_*KH_*S_*HD_];
__device__ float g_o   [(size_t)M_*E_];
__device__ float g_h2  [(size_t)M_*E_];
__device__ float g_g   [(size_t)M_*E_];
__device__ float g_gate[(size_t)M_*F_];
__device__ float g_up  [(size_t)M_*F_];

// ============================================================
// RMSNorm: one block per row of 2048
// ============================================================
__global__ __launch_bounds__(256) void rmsnorm_kernel(
    const float* __restrict__ x, const float* __restrict__ w, float* __restrict__ o)
{
    const int tid = threadIdx.x;
    const size_t base = (size_t)blockIdx.x * E_;
    float4 v0 = *reinterpret_cast<const float4*>(x + base + tid*4);
    float4 v1 = *reinterpret_cast<const float4*>(x + base + 1024 + tid*4);
    float ss = v0.x*v0.x + v0.y*v0.y + v0.z*v0.z + v0.w*v0.w
             + v1.x*v1.x + v1.y*v1.y + v1.z*v1.z + v1.w*v1.w;
    #pragma unroll
    for (int off = 16; off; off >>= 1) ss += __shfl_xor_sync(0xffffffffu, ss, off);
    __shared__ float sred[8];
    if ((tid & 31) == 0) sred[tid >> 5] = ss;
    __syncthreads();
    float tot = 0.f;
    #pragma unroll
    for (int i = 0; i < 8; i++) tot += sred[i];
    float inv = rsqrtf(tot * (1.0f / (float)E_) + 1e-5f);
    float4 w0 = *reinterpret_cast<const float4*>(w + tid*4);
    float4 w1 = *reinterpret_cast<const float4*>(w + 1024 + tid*4);
    float4 o0 = make_float4(v0.x*inv*w0.x, v0.y*inv*w0.y, v0.z*inv*w0.z, v0.w*inv*w0.w);
    float4 o1 = make_float4(v1.x*inv*w1.x, v1.y*inv*w1.y, v1.z*inv*w1.z, v1.w*inv*w1.w);
    *reinterpret_cast<float4*>(o + base + tid*4)        = o0;
    *reinterpret_cast<float4*>(o + base + 1024 + tid*4) = o1;
}

// -------- fp16 mma helpers --------
__device__ __forceinline__ void mma_f16(float* c,
    uint32_t a0, uint32_t a1, uint32_t a2, uint32_t a3,
    uint32_t b0, uint32_t b1)
{
    asm volatile(
        "mma.sync.aligned.m16n8k16.row.col.f32.f16.f16.f32 "
        "{%0,%1,%2,%3}, {%4,%5,%6,%7}, {%8,%9}, {%0,%1,%2,%3};"
        : "+f"(c[0]), "+f"(c[1]), "+f"(c[2]), "+f"(c[3])
        : "r"(a0), "r"(a1), "r"(a2), "r"(a3), "r"(b0), "r"(b1));
}

// store float4 (k0..k0+3 of a 16-wide row) into k-interleaved half layout:
// halves positions [0..15] hold ks {0,1,8,9, 2,3,10,11, 4,5,12,13, 6,7,14,15}
// so that an LDS.64 at half-offset 4t yields {2t,2t+1, 2t+8,2t+9} = (a0/b0, a2/b1)
__device__ __forceinline__ void st_half4_perm(__half* rowp, int k0in, float4 v) {
    __half2* p = reinterpret_cast<__half2*>(rowp);
    const int h2i = (k0in & 7) + (k0in >> 3);   // 0->0, 4->4, 8->1, 12->5
    p[h2i]     = __floats2half2_rn(v.x, v.y);
    p[h2i + 2] = __floats2half2_rn(v.z, v.w);
}

// ============================================================
// FP16 tensor-core GEMM NT: C[M,N] = A[M,K]*B[N,K]^T (+res), f32 accum.
// Block 128x128, K-tile 32 (2 x k16), 256 thr (8 warps: 4 along M x 2 along N),
// warp tile 32x64 (mi=2 x ni=8 of m16n8k16). Double-buffered, reg-staged.
// Requires M%128==0, N%128==0, K%32==0.
// ============================================================
template<bool RES>
__global__ __launch_bounds__(256, 2) void hgemm_nt(
    const float* __restrict__ A, const float* __restrict__ B,
    const float* __restrict__ Res, float* __restrict__ C,
    int M, int N, int K)
{
    // [stage][kk][row][k16]  — row pitch 32B, conflict-free LDS.64 frag loads
    __shared__ __align__(16) __half As[2][2][128][16];
    __shared__ __align__(16) __half Bs[2][2][128][16];

    const int tid  = threadIdx.x;
    const int lane = tid & 31;
    const int warp = tid >> 5;
    const int bm = blockIdx.y * 128;
    const int bn = blockIdx.x * 128;

    const int m0 = (warp & 3) * 32;
    const int n0 = (warp >> 2) * 64;

    // loader: per k-tile of 32, A is 128x32 floats = 1024 float4; 256 thr x 4.
    // f = tid + it*256 -> row = (tid>>3) + it*32, k0 = (tid&7)*4
    const int rowb = tid >> 3;          // 0..31
    const int k0   = (tid & 7) * 4;     // 0,4,...,28
    const int kk_l  = k0 >> 4;          // which k16 sub-tile
    const int k0in  = k0 & 15;

    const float* Ag = A + (size_t)bm * K + k0;
    const float* Bg = B + (size_t)bn * K + k0;

    float acc[2][8][4];
    #pragma unroll
    for (int i = 0; i < 2; i++)
        #pragma unroll
        for (int j = 0; j < 8; j++)
            acc[i][j][0] = acc[i][j][1] = acc[i][j][2] = acc[i][j][3] = 0.f;

    // preload k-tile 0
    #pragma unroll
    for (int it = 0; it < 4; it++) {
        const int r = rowb + it * 32;
        float4 a = *reinterpret_cast<const float4*>(Ag + (size_t)r * K);
        float4 b = *reinterpret_cast<const float4*>(Bg + (size_t)r * K);
        st_half4_perm(&As[0][kk_l][r][0], k0in, a);
        st_half4_perm(&Bs[0][kk_l][r][0], k0in, b);
    }
    __syncthreads();

    const int gr = lane >> 2;   // 0..7
    const int tq = lane & 3;    // 0..3
    const int KT = K >> 5;

    for (int kt = 0; kt < KT; ++kt) {
        const int buf = kt & 1;
        const bool pf = (kt + 1 < KT);
        float4 pa[4], pb[4];
        if (pf) {
            #pragma unroll
            for (int it = 0; it < 4; it++) {
                const int r = rowb + it * 32;
                pa[it] = *reinterpret_cast<const float4*>(Ag + (size_t)r * K + (size_t)(kt + 1) * 32);
                pb[it] = *reinterpret_cast<const float4*>(Bg + (size_t)r * K + (size_t)(kt + 1) * 32);
            }
        }

        #pragma unroll
        for (int kk = 0; kk < 2; ++kk) {
            uint2 ax[2], ay[2];
            #pragma unroll
            for (int mi = 0; mi < 2; mi++) {
                const int r = m0 + mi * 16 + gr;
                ax[mi] = *reinterpret_cast<const uint2*>(&As[buf][kk][r    ][tq * 4]);
                ay[mi] = *reinterpret_cast<const uint2*>(&As[buf][kk][r + 8][tq * 4]);
            }
            #pragma unroll
            for (int ni = 0; ni < 8; ni++) {
                const uint2 bv = *reinterpret_cast<const uint2*>(&Bs[buf][kk][n0 + ni * 8 + gr][tq * 4]);
                #pragma unroll
                for (int mi = 0; mi < 2; mi++)
                    mma_f16(acc[mi][ni], ax[mi].x, ay[mi].x, ax[mi].y, ay[mi].y, bv.x, bv.y);
            }
        }

        if (pf) {
            const int nxt = buf ^ 1;
            #pragma unroll
            for (int it = 0; it < 4; it++) {
                const int r = rowb + it * 32;
                st_half4_perm(&As[nxt][kk_l][r][0], k0in, pa[it]);
                st_half4_perm(&Bs[nxt][kk_l][r][0], k0in, pb[it]);
            }
            __syncthreads();
        }
    }

    // epilogue: c0,c1 at (gr, 2tq),(gr, 2tq+1); c2,c3 at row gr+8
    const int gc = tq * 2;
    #pragma unroll
    for (int mi = 0; mi < 2; mi++) {
        #pragma unroll
        for (int ni = 0; ni < 8; ni++) {
            const int r = bm + m0 + mi * 16 + gr;
            const int c = bn + n0 + ni * 8 + gc;
            float2 lo = make_float2(acc[mi][ni][0], acc[mi][ni][1]);
            float2 hi = make_float2(acc[mi][ni][2], acc[mi][ni][3]);
            if (RES) {
                float2 rlo = *reinterpret_cast<const float2*>(Res + (size_t)r * N + c);
                float2 rhi = *reinterpret_cast<const float2*>(Res + (size_t)(r + 8) * N + c);
                lo.x += rlo.x; lo.y += rlo.y;
                hi.x += rhi.x; hi.y += rhi.y;
            }
            *reinterpret_cast<float2*>(C + (size_t)r * N + c)       = lo;
            *reinterpret_cast<float2*>(C + (size_t)(r + 8) * N + c) = hi;
        }
    }
}

// ============================================================
// RoPE + head reshape. qkv [M_, 3072] -> q[B,H,S,HD], k/v[B,KH,S,HD]
// ============================================================
__global__ __launch_bounds__(256) void rope_reshape_kernel(
    const float* __restrict__ qkv, const float* __restrict__ fc,
    float* __restrict__ qr, float* __restrict__ kr, float* __restrict__ vr)
{
    const int gid = blockIdx.x * 256 + threadIdx.x;
    if (gid >= M_ * (QKVN/2)) return;
    const int row = gid / (QKVN/2);
    const int col = (gid - row * (QKVN/2)) * 2;
    const int b = row >> 11;
    const int s = row & (S_-1);
    const float* src = qkv + (size_t)row * QKVN + col;
    const float x0 = src[0], x1 = src[1];

    if (col < E_) {
        const int hh = col >> 6, d = col & 63;
        const float c = fc[s*64 + d], sn = fc[s*64 + d + 1];
        float* dst = qr + ((((size_t)b*H_ + hh) * S_ + s) << 6) + d;
        dst[0] = x0*c - x1*sn; dst[1] = x1*c + x0*sn;
    } else if (col < E_ + KV_) {
        const int kc = col - E_;
        const int kh = kc >> 6, d = kc & 63;
        const float c = fc[s*64 + d], sn = fc[s*64 + d + 1];
        float* dst = kr + ((((size_t)b*KH_ + kh) * S_ + s) << 6) + d;
        dst[0] = x0*c - x1*sn; dst[1] = x1*c + x0*sn;
    } else {
        const int vc = col - E_ - KV_;
        const int kh = vc >> 6, d = vc & 63;
        float* dst = vr + ((((size_t)b*KH_ + kh) * S_ + s) << 6) + d;
        dst[0] = x0; dst[1] = x1;
    }
}

// ============================================================
// Flash attention fp32, causal, GQA 4:1. 64x64 tiles, 256 thr.
// ============================================================
__global__ __launch_bounds__(256) void attn_kernel(
    const float* __restrict__ qr, const float* __restrict__ kr,
    const float* __restrict__ vr, float* __restrict__ of)
{
    extern __shared__ float sm[];
    float* sQ = sm;
    float* sK = sm + 64*68;
    float* sV = sm + 2*64*68;
    float* sP = sm + 3*64*68;

    const int tid = threadIdx.x;
    const int qt = blockIdx.x, h = blockIdx.y, b = blockIdx.z;
    const int kvh = h >> 2;
    const float* Q = qr + (((size_t)(b*H_ + h)) * S_ + qt*64) * HD_;
    const float* K = kr + ((size_t)(b*KH_ + kvh)) * S_ * HD_;
    const float* V = vr + ((size_t)(b*KH_ + kvh)) * S_ * HD_;

    #pragma unroll
    for (int i = 0; i < 4; i++) {
        const int id = tid + i*256;
        const int r = id >> 4, c = (id & 15) * 4;
        *reinterpret_cast<float4*>(&sQ[r*68 + c]) =
            *reinterpret_cast<const float4*>(Q + r*64 + c);
    }
    const int tr = tid >> 4, tc = tid & 15;

    float m_i[4], l_i[4], acc[4][4];
    #pragma unroll
    for (int i = 0; i < 4; i++) {
        m_i[i] = -1e30f; l_i[i] = 0.f;
        acc[i][0] = acc[i][1] = acc[i][2] = acc[i][3] = 0.f;
    }

    for (int kt = 0; kt <= qt; ++kt) {
        __syncthreads();
        #pragma unroll
        for (int i = 0; i < 4; i++) {
            const int id = tid + i*256;
            const int r = id >> 4, c = (id & 15) * 4;
            *reinterpret_cast<float4*>(&sK[r*68 + c]) =
                *reinterpret_cast<const float4*>(K + ((size_t)kt*64 + r)*64 + c);
            *reinterpret_cast<float4*>(&sV[r*68 + c]) =
                *reinterpret_cast<const float4*>(V + ((size_t)kt*64 + r)*64 + c);
        }
        __syncthreads();

        float s[4][4] = {{0.f,0.f,0.f,0.f},{0.f,0.f,0.f,0.f},{0.f,0.f,0.f,0.f},{0.f,0.f,0.f,0.f}};
        #pragma unroll
        for (int d = 0; d < 64; d += 4) {
            float4 a[4], bb[4];
            #pragma unroll
            for (int i = 0; i < 4; i++) a[i]  = *reinterpret_cast<const float4*>(&sQ[(tr*4+i)*68 + d]);
            #pragma unroll
            for (int j = 0; j < 4; j++) bb[j] = *reinterpret_cast<const float4*>(&sK[(tc*4+j)*68 + d]);
            #pragma unroll
            for (int i = 0; i < 4; i++)
                #pragma unroll
                for (int j = 0; j < 4; j++)
                    s[i][j] += a[i].x*bb[j].x + a[i].y*bb[j].y + a[i].z*bb[j].z + a[i].w*bb[j].w;
        }

        const bool diag = (kt == qt);
        #pragma unroll
        for (int i = 0; i < 4; i++) {
            float p[4];
            #pragma unroll
            for (int j = 0; j < 4; j++) {
                float val = s[i][j] * 0.125f;
                if (diag && (tc*4 + j) > (tr*4 + i)) val = -1e30f;
                s[i][j] = val;
            }
            float mx = fmaxf(fmaxf(s[i][0], s[i][1]), fmaxf(s[i][2], s[i][3]));
            #pragma unroll
            for (int off = 8; off; off >>= 1) mx = fmaxf(mx, __shfl_xor_sync(0xffffffffu, mx, off));
            const float mn = fmaxf(m_i[i], mx);
            const float alpha = __expf(m_i[i] - mn);
            float ts = 0.f;
            #pragma unroll
            for (int j = 0; j < 4; j++) { p[j] = __expf(s[i][j] - mn); ts += p[j]; }
            #pragma unroll
            for (int off = 8; off; off >>= 1) ts += __shfl_xor_sync(0xffffffffu, ts, off);
            l_i[i] = l_i[i] * alpha + ts;
            m_i[i] = mn;
            acc[i][0] *= alpha; acc[i][1] *= alpha; acc[i][2] *= alpha; acc[i][3] *= alpha;
            *reinterpret_cast<float4*>(&sP[(tr*4+i)*68 + tc*4]) = make_float4(p[0], p[1], p[2], p[3]);
        }
        __syncthreads();

        #pragma unroll 4
        for (int k = 0; k < 64; k++) {
            const float4 vv = *reinterpret_cast<const float4*>(&sV[k*68 + tc*4]);
            #pragma unroll
            for (int i = 0; i < 4; i++) {
                const float pk = sP[(tr*4+i)*68 + k];
                acc[i][0] = fmaf(pk, vv.x, acc[i][0]);
                acc[i][1] = fmaf(pk, vv.y, acc[i][1]);
                acc[i][2] = fmaf(pk, vv.z, acc[i][2]);
                acc[i][3] = fmaf(pk, vv.w, acc[i][3]);
            }
        }
    }

    #pragma unroll
    for (int i = 0; i < 4; i++) {
        const float inv = 1.0f / l_i[i];
        const size_t row = (size_t)b * S_ + qt*64 + tr*4 + i;
        float4 o = make_float4(acc[i][0]*inv, acc[i][1]*inv, acc[i][2]*inv, acc[i][3]*inv);
        *reinterpret_cast<float4*>(of + row * E_ + h*64 + tc*4) = o;
    }
}

// ============================================================
// SwiGLU: gate = silu(gate) * up   (in place)
// ============================================================
__global__ __launch_bounds__(256) void silu_mul_kernel(
    float* __restrict__ gate, const float* __restrict__ up)
{
    const size_t i = ((size_t)blockIdx.x * 256 + threadIdx.x) * 4;
    float4 g = *reinterpret_cast<float4*>(gate + i);
    float4 u = *reinterpret_cast<const float4*>(up + i);
    g.x = g.x * u.x / (1.f + __expf(-g.x));
    g.y = g.y * u.y / (1.f + __expf(-g.y));
    g.z = g.z * u.z / (1.f + __expf(-g.z));
    g.w = g.w * u.w / (1.f + __expf(-g.w));
    *reinterpret_cast<float4*>(gate + i) = g;
}

// ============================================================
// launch
// ============================================================
extern "C" void kernel_launch(void* const* d_in, const int* in_sizes, int n_in,
                              void* d_out, int out_size)
{
    (void)in_sizes; (void)n_in; (void)out_size;
    const float* x     = (const float*)d_in[0];
    const float* fc    = (const float*)d_in[2];
    const float* w_qkv = (const float*)d_in[3];
    const float* w_o   = (const float*)d_in[4];
    const float* w1    = (const float*)d_in[5];
    const float* w2    = (const float*)d_in[6];
    const float* w3    = (const float*)d_in[7];
    const float* anw   = (const float*)d_in[8];
    const float* fnw   = (const float*)d_in[9];
    float* out = (float*)d_out;

    float *h, *qkv, *q, *k, *v, *o, *h2, *g, *gate, *up;
    cudaGetSymbolAddress((void**)&h,    g_h);
    cudaGetSymbolAddress((void**)&qkv,  g_qkv);
    cudaGetSymbolAddress((void**)&q,    g_q);
    cudaGetSymbolAddress((void**)&k,    g_k);
    cudaGetSymbolAddress((void**)&v,    g_v);
    cudaGetSymbolAddress((void**)&o,    g_o);
    cudaGetSymbolAddress((void**)&h2,   g_h2);
    cudaGetSymbolAddress((void**)&g,    g_g);
    cudaGetSymbolAddress((void**)&gate, g_gate);
    cudaGetSymbolAddress((void**)&up,   g_up);

    cudaFuncSetAttribute(attn_kernel, cudaFuncAttributeMaxDynamicSharedMemorySize, 4*64*68*4);

    // 1. attn rmsnorm
    rmsnorm_kernel<<<M_, 256>>>(x, anw, h);
    // 2. qkv = h @ w_qkv^T
    hgemm_nt<false><<<dim3(QKVN/128, M_/128), 256>>>(h, w_qkv, nullptr, qkv, M_, QKVN, E_);
    // 3. rope + reshape
    rope_reshape_kernel<<<(M_*(QKVN/2))/256, 256>>>(qkv, fc, q, k, v);
    // 4. attention
    attn_kernel<<<dim3(S_/64, H_, B_), 256, 4*64*68*4>>>(q, k, v, o);
    // 5. h2 = x + o @ w_o^T
    hgemm_nt<true><<<dim3(E_/128, M_/128), 256>>>(o, w_o, x, h2, M_, E_, E_);
    // 6. ffn rmsnorm
    rmsnorm_kernel<<<M_, 256>>>(h2, fnw, g);
    // 7. gate / up projections
    hgemm_nt<false><<<dim3(F_/128, M_/128), 256>>>(g, w1, nullptr, gate, M_, F_, E_);
    hgemm_nt<false><<<dim3(F_/128, M_/128), 256>>>(g, w3, nullptr, up,   M_, F_, E_);
    // 8. swiglu
    silu_mul_kernel<<<((size_t)M_*F_/4)/256, 256>>>(gate, up);
    // 9. out = h2 + act @ w2^T
    hgemm_nt<true><<<dim3(E_/128, M_/128), 256>>>(gate, w2, h2, out, M_, E_, F_);
}

// round 6
// speedup vs baseline: 4.4085x; 1.6140x over previous
#include <cuda_runtime.h>
#include <cuda_fp16.h>
#include <cstdint>

// Problem constants
#define B_    2
#define S_    2048
#define E_    2048
#define H_    32
#define KH_   8
#define HD_   64
#define F_    8192
#define KV_   (KH_*HD_)      // 512
#define QKVN  (E_ + 2*KV_)   // 3072
#define M_    (B_*S_)        // 4096

// -------- scratch (device globals: allocation-free) --------
__device__ float g_h   [(size_t)M_*E_];
__device__ float g_qkv [(size_t)M_*QKVN];
__device__ __half g_qh [(size_t)B_*H_ *S_*HD_];
__device__ __half g_kh [(size_t)B_*KH_*S_*HD_];
__device__ __half g_vh [(size_t)B_*KH_*S_*HD_];
__device__ float g_o   [(size_t)M_*E_];
__device__ float g_h2  [(size_t)M_*E_];
__device__ float g_g   [(size_t)M_*E_];
__device__ float g_gate[(size_t)M_*F_];
__device__ float g_up  [(size_t)M_*F_];

__device__ __forceinline__ uint32_t smem_u32(const void* p) {
    uint32_t a;
    asm("{ .reg .u64 t; cvta.to.shared.u64 t, %1; cvt.u32.u64 %0, t; }" : "=r"(a) : "l"(p));
    return a;
}
__device__ __forceinline__ uint32_t packh2(float a, float b) {
    __half2 h = __floats2half2_rn(a, b);
    return *reinterpret_cast<uint32_t*>(&h);
}

// ============================================================
// RMSNorm: one block per row of 2048
// ============================================================
__global__ __launch_bounds__(256) void rmsnorm_kernel(
    const float* __restrict__ x, const float* __restrict__ w, float* __restrict__ o)
{
    const int tid = threadIdx.x;
    const size_t base = (size_t)blockIdx.x * E_;
    float4 v0 = *reinterpret_cast<const float4*>(x + base + tid*4);
    float4 v1 = *reinterpret_cast<const float4*>(x + base + 1024 + tid*4);
    float ss = v0.x*v0.x + v0.y*v0.y + v0.z*v0.z + v0.w*v0.w
             + v1.x*v1.x + v1.y*v1.y + v1.z*v1.z + v1.w*v1.w;
    #pragma unroll
    for (int off = 16; off; off >>= 1) ss += __shfl_xor_sync(0xffffffffu, ss, off);
    __shared__ float sred[8];
    if ((tid & 31) == 0) sred[tid >> 5] = ss;
    __syncthreads();
    float tot = 0.f;
    #pragma unroll
    for (int i = 0; i < 8; i++) tot += sred[i];
    float inv = rsqrtf(tot * (1.0f / (float)E_) + 1e-5f);
    float4 w0 = *reinterpret_cast<const float4*>(w + tid*4);
    float4 w1 = *reinterpret_cast<const float4*>(w + 1024 + tid*4);
    float4 o0 = make_float4(v0.x*inv*w0.x, v0.y*inv*w0.y, v0.z*inv*w0.z, v0.w*inv*w0.w);
    float4 o1 = make_float4(v1.x*inv*w1.x, v1.y*inv*w1.y, v1.z*inv*w1.z, v1.w*inv*w1.w);
    *reinterpret_cast<float4*>(o + base + tid*4)        = o0;
    *reinterpret_cast<float4*>(o + base + 1024 + tid*4) = o1;
}

// -------- fp16 mma helpers --------
__device__ __forceinline__ void mma_f16(float* c,
    uint32_t a0, uint32_t a1, uint32_t a2, uint32_t a3,
    uint32_t b0, uint32_t b1)
{
    asm volatile(
        "mma.sync.aligned.m16n8k16.row.col.f32.f16.f16.f32 "
        "{%0,%1,%2,%3}, {%4,%5,%6,%7}, {%8,%9}, {%0,%1,%2,%3};"
        : "+f"(c[0]), "+f"(c[1]), "+f"(c[2]), "+f"(c[3])
        : "r"(a0), "r"(a1), "r"(a2), "r"(a3), "r"(b0), "r"(b1));
}

// store float4 (k0..k0+3 of a 16-wide row) into k-interleaved half layout
__device__ __forceinline__ void st_half4_perm(__half* rowp, int k0in, float4 v) {
    __half2* p = reinterpret_cast<__half2*>(rowp);
    const int h2i = (k0in & 7) + (k0in >> 3);   // 0->0, 4->4, 8->1, 12->5
    p[h2i]     = __floats2half2_rn(v.x, v.y);
    p[h2i + 2] = __floats2half2_rn(v.z, v.w);
}

// ============================================================
// FP16 tensor-core GEMM NT (unchanged from R4)
// ============================================================
template<bool RES>
__global__ __launch_bounds__(256, 2) void hgemm_nt(
    const float* __restrict__ A, const float* __restrict__ B,
    const float* __restrict__ Res, float* __restrict__ C,
    int M, int N, int K)
{
    __shared__ __align__(16) __half As[2][2][128][16];
    __shared__ __align__(16) __half Bs[2][2][128][16];

    const int tid  = threadIdx.x;
    const int lane = tid & 31;
    const int warp = tid >> 5;
    const int bm = blockIdx.y * 128;
    const int bn = blockIdx.x * 128;

    const int m0 = (warp & 3) * 32;
    const int n0 = (warp >> 2) * 64;

    const int rowb = tid >> 3;
    const int k0   = (tid & 7) * 4;
    const int kk_l  = k0 >> 4;
    const int k0in  = k0 & 15;

    const float* Ag = A + (size_t)bm * K + k0;
    const float* Bg = B + (size_t)bn * K + k0;

    float acc[2][8][4];
    #pragma unroll
    for (int i = 0; i < 2; i++)
        #pragma unroll
        for (int j = 0; j < 8; j++)
            acc[i][j][0] = acc[i][j][1] = acc[i][j][2] = acc[i][j][3] = 0.f;

    #pragma unroll
    for (int it = 0; it < 4; it++) {
        const int r = rowb + it * 32;
        float4 a = *reinterpret_cast<const float4*>(Ag + (size_t)r * K);
        float4 b = *reinterpret_cast<const float4*>(Bg + (size_t)r * K);
        st_half4_perm(&As[0][kk_l][r][0], k0in, a);
        st_half4_perm(&Bs[0][kk_l][r][0], k0in, b);
    }
    __syncthreads();

    const int gr = lane >> 2;
    const int tq = lane & 3;
    const int KT = K >> 5;

    for (int kt = 0; kt < KT; ++kt) {
        const int buf = kt & 1;
        const bool pf = (kt + 1 < KT);
        float4 pa[4], pb[4];
        if (pf) {
            #pragma unroll
            for (int it = 0; it < 4; it++) {
                const int r = rowb + it * 32;
                pa[it] = *reinterpret_cast<const float4*>(Ag + (size_t)r * K + (size_t)(kt + 1) * 32);
                pb[it] = *reinterpret_cast<const float4*>(Bg + (size_t)r * K + (size_t)(kt + 1) * 32);
            }
        }

        #pragma unroll
        for (int kk = 0; kk < 2; ++kk) {
            uint2 ax[2], ay[2];
            #pragma unroll
            for (int mi = 0; mi < 2; mi++) {
                const int r = m0 + mi * 16 + gr;
                ax[mi] = *reinterpret_cast<const uint2*>(&As[buf][kk][r    ][tq * 4]);
                ay[mi] = *reinterpret_cast<const uint2*>(&As[buf][kk][r + 8][tq * 4]);
            }
            #pragma unroll
            for (int ni = 0; ni < 8; ni++) {
                const uint2 bv = *reinterpret_cast<const uint2*>(&Bs[buf][kk][n0 + ni * 8 + gr][tq * 4]);
                #pragma unroll
                for (int mi = 0; mi < 2; mi++)
                    mma_f16(acc[mi][ni], ax[mi].x, ay[mi].x, ax[mi].y, ay[mi].y, bv.x, bv.y);
            }
        }

        if (pf) {
            const int nxt = buf ^ 1;
            #pragma unroll
            for (int it = 0; it < 4; it++) {
                const int r = rowb + it * 32;
                st_half4_perm(&As[nxt][kk_l][r][0], k0in, pa[it]);
                st_half4_perm(&Bs[nxt][kk_l][r][0], k0in, pb[it]);
            }
            __syncthreads();
        }
    }

    const int gc = tq * 2;
    #pragma unroll
    for (int mi = 0; mi < 2; mi++) {
        #pragma unroll
        for (int ni = 0; ni < 8; ni++) {
            const int r = bm + m0 + mi * 16 + gr;
            const int c = bn + n0 + ni * 8 + gc;
            float2 lo = make_float2(acc[mi][ni][0], acc[mi][ni][1]);
            float2 hi = make_float2(acc[mi][ni][2], acc[mi][ni][3]);
            if (RES) {
                float2 rlo = *reinterpret_cast<const float2*>(Res + (size_t)r * N + c);
                float2 rhi = *reinterpret_cast<const float2*>(Res + (size_t)(r + 8) * N + c);
                lo.x += rlo.x; lo.y += rlo.y;
                hi.x += rhi.x; hi.y += rhi.y;
            }
            *reinterpret_cast<float2*>(C + (size_t)r * N + c)       = lo;
            *reinterpret_cast<float2*>(C + (size_t)(r + 8) * N + c) = hi;
        }
    }
}

// ============================================================
// RoPE + head reshape -> fp16 q(pre-scaled by 0.125)/k/v
// ============================================================
__global__ __launch_bounds__(256) void rope_reshape_kernel(
    const float* __restrict__ qkv, const float* __restrict__ fc,
    __half* __restrict__ qr, __half* __restrict__ kr, __half* __restrict__ vr)
{
    const int gid = blockIdx.x * 256 + threadIdx.x;
    if (gid >= M_ * (QKVN/2)) return;
    const int row = gid / (QKVN/2);
    const int col = (gid - row * (QKVN/2)) * 2;
    const int b = row >> 11;
    const int s = row & (S_-1);
    const float* src = qkv + (size_t)row * QKVN + col;
    const float x0 = src[0], x1 = src[1];

    if (col < E_) {
        const int hh = col >> 6, d = col & 63;
        const float c = fc[s*64 + d], sn = fc[s*64 + d + 1];
        __half2* dst = reinterpret_cast<__half2*>(qr + ((((size_t)b*H_ + hh) * S_ + s) << 6) + d);
        *dst = __floats2half2_rn((x0*c - x1*sn) * 0.125f, (x1*c + x0*sn) * 0.125f);
    } else if (col < E_ + KV_) {
        const int kc = col - E_;
        const int kh = kc >> 6, d = kc & 63;
        const float c = fc[s*64 + d], sn = fc[s*64 + d + 1];
        __half2* dst = reinterpret_cast<__half2*>(kr + ((((size_t)b*KH_ + kh) * S_ + s) << 6) + d);
        *dst = __floats2half2_rn(x0*c - x1*sn, x1*c + x0*sn);
    } else {
        const int vc = col - E_ - KV_;
        const int kh = vc >> 6, d = vc & 63;
        __half2* dst = reinterpret_cast<__half2*>(vr + ((((size_t)b*KH_ + kh) * S_ + s) << 6) + d);
        *dst = __floats2half2_rn(x0, x1);
    }
}

// ============================================================
// Flash attention, fp16 mma, causal, GQA 4:1.
// 64 q-rows x 64 k-cols per block, 128 thr (4 warps, 16 q-rows each).
// ============================================================
#define VPITCH 72
__global__ __launch_bounds__(128) void attn_mma_kernel(
    const __half* __restrict__ qr, const __half* __restrict__ kr,
    const __half* __restrict__ vr, float* __restrict__ of)
{
    __shared__ __align__(16) __half sQ[4][64][16];   // [k16-group][row][perm]
    __shared__ __align__(16) __half sK[4][64][16];
    __shared__ __align__(16) __half sV[64][VPITCH];  // row-major seq x hd

    const int tid  = threadIdx.x;
    const int lane = tid & 31, warp = tid >> 5;
    const int qt = blockIdx.x, h = blockIdx.y, b = blockIdx.z;
    const int kvh = h >> 2;
    const __half* Q = qr + (((size_t)(b*H_ + h)) * S_ + qt*64) * HD_;
    const __half* K = kr + ((size_t)(b*KH_ + kvh)) * S_ * HD_;
    const __half* V = vr + ((size_t)(b*KH_ + kvh)) * S_ * HD_;

    // load Q tile once (perm layout). 64 rows x 8 uint4-segs = 512; 128 thr x 4.
    // r = f>>3 (0..63), seg = f&7 (0..7): 8 halves per seg.
    #pragma unroll
    for (int it = 0; it < 4; it++) {
        const int f = tid + it*128;
        const int r = f >> 3, seg = f & 7;
        const int g = seg >> 1, hp = seg & 1;
        uint4 v4 = *reinterpret_cast<const uint4*>(Q + (size_t)r*64 + seg*8);
        uint32_t* p = reinterpret_cast<uint32_t*>(&sQ[g][r][0]);
        p[hp] = v4.x; p[hp+2] = v4.y; p[hp+4] = v4.z; p[hp+6] = v4.w;
    }

    const int gr = lane >> 2;       // 0..7
    const int tq = lane & 3;        // 0..3
    const int qrow = warp * 16;
    // ldmatrix lane address offsets within V tile
    const int lm_r = (lane & 7) + ((lane >> 3) & 1) * 8;
    const int lm_c = ((lane >> 4) & 1) * 8;

    float m0 = -1e30f, m1 = -1e30f, l0 = 0.f, l1 = 0.f;
    float oac[8][4];
    #pragma unroll
    for (int i = 0; i < 8; i++)
        oac[i][0] = oac[i][1] = oac[i][2] = oac[i][3] = 0.f;

    for (int kt = 0; kt <= qt; ++kt) {
        __syncthreads();
        #pragma unroll
        for (int it = 0; it < 4; it++) {
            const int f = tid + it*128;
            const int r = f >> 3, seg = f & 7;
            const int g = seg >> 1, hp = seg & 1;
            uint4 kv4 = *reinterpret_cast<const uint4*>(K + ((size_t)kt*64 + r)*64 + seg*8);
            uint32_t* p = reinterpret_cast<uint32_t*>(&sK[g][r][0]);
            p[hp] = kv4.x; p[hp+2] = kv4.y; p[hp+4] = kv4.z; p[hp+6] = kv4.w;
            uint4 vv4 = *reinterpret_cast<const uint4*>(V + ((size_t)kt*64 + r)*64 + seg*8);
            *reinterpret_cast<uint4*>(&sV[r][seg*8]) = vv4;
        }
        __syncthreads();

        // ---- S = Q K^T ----
        float sc[8][4];
        #pragma unroll
        for (int i = 0; i < 8; i++)
            sc[i][0] = sc[i][1] = sc[i][2] = sc[i][3] = 0.f;
        #pragma unroll
        for (int kk = 0; kk < 4; kk++) {
            const uint2 alo = *reinterpret_cast<const uint2*>(&sQ[kk][qrow + gr    ][tq*4]);
            const uint2 ahi = *reinterpret_cast<const uint2*>(&sQ[kk][qrow + gr + 8][tq*4]);
            #pragma unroll
            for (int ni = 0; ni < 8; ni++) {
                const uint2 bv = *reinterpret_cast<const uint2*>(&sK[kk][ni*8 + gr][tq*4]);
                mma_f16(sc[ni], alo.x, ahi.x, alo.y, ahi.y, bv.x, bv.y);
            }
        }

        // ---- causal mask on diagonal tile ----
        if (kt == qt) {
            const int lr0 = qrow + gr, lr1 = lr0 + 8;
            #pragma unroll
            for (int ni = 0; ni < 8; ni++) {
                const int c0 = ni*8 + tq*2, c1 = c0 + 1;
                if (c0 > lr0) sc[ni][0] = -1e30f;
                if (c1 > lr0) sc[ni][1] = -1e30f;
                if (c0 > lr1) sc[ni][2] = -1e30f;
                if (c1 > lr1) sc[ni][3] = -1e30f;
            }
        }

        // ---- online softmax ----
        float mx0 = -1e30f, mx1 = -1e30f;
        #pragma unroll
        for (int ni = 0; ni < 8; ni++) {
            mx0 = fmaxf(mx0, fmaxf(sc[ni][0], sc[ni][1]));
            mx1 = fmaxf(mx1, fmaxf(sc[ni][2], sc[ni][3]));
        }
        mx0 = fmaxf(mx0, __shfl_xor_sync(0xffffffffu, mx0, 1));
        mx0 = fmaxf(mx0, __shfl_xor_sync(0xffffffffu, mx0, 2));
        mx1 = fmaxf(mx1, __shfl_xor_sync(0xffffffffu, mx1, 1));
        mx1 = fmaxf(mx1, __shfl_xor_sync(0xffffffffu, mx1, 2));
        const float nm0 = fmaxf(m0, mx0), nm1 = fmaxf(m1, mx1);
        const float al0 = __expf(m0 - nm0), al1 = __expf(m1 - nm1);
        m0 = nm0; m1 = nm1;

        float s0 = 0.f, s1 = 0.f;
        uint32_t pa[4][4];
        #pragma unroll
        for (int ni = 0; ni < 8; ni++) {
            const float p0 = __expf(sc[ni][0] - nm0);
            const float p1 = __expf(sc[ni][1] - nm0);
            const float p2 = __expf(sc[ni][2] - nm1);
            const float p3 = __expf(sc[ni][3] - nm1);
            s0 += p0 + p1; s1 += p2 + p3;
            const int kk = ni >> 1, w2 = (ni & 1) * 2;
            pa[kk][w2    ] = packh2(p0, p1);   // a0 (ni even) / a2 (ni odd)
            pa[kk][w2 + 1] = packh2(p2, p3);   // a1 / a3
        }
        s0 += __shfl_xor_sync(0xffffffffu, s0, 1);
        s0 += __shfl_xor_sync(0xffffffffu, s0, 2);
        s1 += __shfl_xor_sync(0xffffffffu, s1, 1);
        s1 += __shfl_xor_sync(0xffffffffu, s1, 2);
        l0 = l0 * al0 + s0;
        l1 = l1 * al1 + s1;
        #pragma unroll
        for (int ni = 0; ni < 8; ni++) {
            oac[ni][0] *= al0; oac[ni][1] *= al0;
            oac[ni][2] *= al1; oac[ni][3] *= al1;
        }

        // ---- O += P V ----
        #pragma unroll
        for (int kk = 0; kk < 4; kk++) {
            uint32_t bfr[8][2];
            #pragma unroll
            for (int nip = 0; nip < 4; nip++) {
                const uint32_t addr = smem_u32(&sV[16*kk + lm_r][nip*16 + lm_c]);
                asm volatile(
                    "ldmatrix.sync.aligned.m8n8.x4.trans.shared.b16 {%0,%1,%2,%3}, [%4];"
                    : "=r"(bfr[2*nip][0]), "=r"(bfr[2*nip][1]),
                      "=r"(bfr[2*nip+1][0]), "=r"(bfr[2*nip+1][1])
                    : "r"(addr));
            }
            #pragma unroll
            for (int ni = 0; ni < 8; ni++)
                mma_f16(oac[ni], pa[kk][0], pa[kk][1], pa[kk][2], pa[kk][3],
                        bfr[ni][0], bfr[ni][1]);
        }
    }

    // ---- write O (fp32, [token][h*64+hd]) ----
    const float il0 = 1.0f / l0, il1 = 1.0f / l1;
    const size_t row0 = (size_t)b * S_ + qt*64 + qrow + gr;
    float* o0 = of + row0 * E_ + h*64;
    float* o1 = o0 + (size_t)8 * E_;
    #pragma unroll
    for (int ni = 0; ni < 8; ni++) {
        *reinterpret_cast<float2*>(o0 + ni*8 + tq*2) =
            make_float2(oac[ni][0]*il0, oac[ni][1]*il0);
        *reinterpret_cast<float2*>(o1 + ni*8 + tq*2) =
            make_float2(oac[ni][2]*il1, oac[ni][3]*il1);
    }
}

// ============================================================
// SwiGLU: gate = silu(gate) * up   (in place)
// ============================================================
__global__ __launch_bounds__(256) void silu_mul_kernel(
    float* __restrict__ gate, const float* __restrict__ up)
{
    const size_t i = ((size_t)blockIdx.x * 256 + threadIdx.x) * 4;
    float4 g = *reinterpret_cast<float4*>(gate + i);
    float4 u = *reinterpret_cast<const float4*>(up + i);
    g.x = g.x * u.x / (1.f + __expf(-g.x));
    g.y = g.y * u.y / (1.f + __expf(-g.y));
    g.z = g.z * u.z / (1.f + __expf(-g.z));
    g.w = g.w * u.w / (1.f + __expf(-g.w));
    *reinterpret_cast<float4*>(gate + i) = g;
}

// ============================================================
// launch
// ============================================================
extern "C" void kernel_launch(void* const* d_in, const int* in_sizes, int n_in,
                              void* d_out, int out_size)
{
    (void)in_sizes; (void)n_in; (void)out_size;
    const float* x     = (const float*)d_in[0];
    const float* fc    = (const float*)d_in[2];
    const float* w_qkv = (const float*)d_in[3];
    const float* w_o   = (const float*)d_in[4];
    const float* w1    = (const float*)d_in[5];
    const float* w2    = (const float*)d_in[6];
    const float* w3    = (const float*)d_in[7];
    const float* anw   = (const float*)d_in[8];
    const float* fnw   = (const float*)d_in[9];
    float* out = (float*)d_out;

    float *h, *qkv, *o, *h2, *g, *gate, *up;
    __half *qh, *kh, *vh;
    cudaGetSymbolAddress((void**)&h,    g_h);
    cudaGetSymbolAddress((void**)&qkv,  g_qkv);
    cudaGetSymbolAddress((void**)&qh,   g_qh);
    cudaGetSymbolAddress((void**)&kh,   g_kh);
    cudaGetSymbolAddress((void**)&vh,   g_vh);
    cudaGetSymbolAddress((void**)&o,    g_o);
    cudaGetSymbolAddress((void**)&h2,   g_h2);
    cudaGetSymbolAddress((void**)&g,    g_g);
    cudaGetSymbolAddress((void**)&gate, g_gate);
    cudaGetSymbolAddress((void**)&up,   g_up);

    // 1. attn rmsnorm
    rmsnorm_kernel<<<M_, 256>>>(x, anw, h);
    // 2. qkv = h @ w_qkv^T
    hgemm_nt<false><<<dim3(QKVN/128, M_/128), 256>>>(h, w_qkv, nullptr, qkv, M_, QKVN, E_);
    // 3. rope + reshape -> fp16
    rope_reshape_kernel<<<(M_*(QKVN/2))/256, 256>>>(qkv, fc, qh, kh, vh);
    // 4. attention (tensor cores)
    attn_mma_kernel<<<dim3(S_/64, H_, B_), 128>>>(qh, kh, vh, o);
    // 5. h2 = x + o @ w_o^T
    hgemm_nt<true><<<dim3(E_/128, M_/128), 256>>>(o, w_o, x, h2, M_, E_, E_);
    // 6. ffn rmsnorm
    rmsnorm_kernel<<<M_, 256>>>(h2, fnw, g);
    // 7. gate / up projections
    hgemm_nt<false><<<dim3(F_/128, M_/128), 256>>>(g, w1, nullptr, gate, M_, F_, E_);
    hgemm_nt<false><<<dim3(F_/128, M_/128), 256>>>(g, w3, nullptr, up,   M_, F_, E_);
    // 8. swiglu
    silu_mul_kernel<<<((size_t)M_*F_/4)/256, 256>>>(gate, up);
    // 9. out = h2 + act @ w2^T
    hgemm_nt<true><<<dim3(E_/128, M_/128), 256>>>(gate, w2, h2, out, M_, E_, F_);
}

// round 7
// speedup vs baseline: 4.6795x; 1.0615x over previous
#include <cuda_runtime.h>
#include <cuda_fp16.h>
#include <cstdint>

// Problem constants
#define B_    2
#define S_    2048
#define E_    2048
#define H_    32
#define KH_   8
#define HD_   64
#define F_    8192
#define KV_   (KH_*HD_)      // 512
#define QKVN  (E_ + 2*KV_)   // 3072
#define M_    (B_*S_)        // 4096

// -------- scratch (device globals: allocation-free) --------
__device__ __half g_wqkvh[(size_t)QKVN*E_];
__device__ __half g_woh  [(size_t)E_*E_];
__device__ __half g_w1h  [(size_t)F_*E_];
__device__ __half g_w3h  [(size_t)F_*E_];
__device__ __half g_w2h  [(size_t)E_*F_];

__device__ __half g_h    [(size_t)M_*E_];
__device__ __half g_qkvh [(size_t)M_*QKVN];
__device__ __half g_qh   [(size_t)B_*H_ *S_*HD_];
__device__ __half g_kh   [(size_t)B_*KH_*S_*HD_];
__device__ __half g_vh   [(size_t)B_*KH_*S_*HD_];
__device__ __half g_o    [(size_t)M_*E_];
__device__ float  g_h2   [(size_t)M_*E_];
__device__ __half g_g    [(size_t)M_*E_];
__device__ __half g_gate [(size_t)M_*F_];
__device__ __half g_up   [(size_t)M_*F_];

__device__ __forceinline__ uint32_t smem_u32(const void* p) {
    uint32_t a;
    asm("{ .reg .u64 t; cvta.to.shared.u64 t, %1; cvt.u32.u64 %0, t; }" : "=r"(a) : "l"(p));
    return a;
}
__device__ __forceinline__ uint32_t packh2(float a, float b) {
    __half2 h = __floats2half2_rn(a, b);
    return *reinterpret_cast<uint32_t*>(&h);
}
__device__ __forceinline__ float2 unpackh2(uint32_t u) {
    __half2 h = *reinterpret_cast<__half2*>(&u);
    return __half22float2(h);
}

// ============================================================
// fp32 -> fp16 bulk convert (weights). n % 1024 == 0.
// ============================================================
__global__ __launch_bounds__(256) void f2h_kernel(
    const float* __restrict__ in, __half* __restrict__ out)
{
    const size_t i = ((size_t)blockIdx.x * 256 + threadIdx.x) * 4;
    float4 v = *reinterpret_cast<const float4*>(in + i);
    uint2 o = make_uint2(packh2(v.x, v.y), packh2(v.z, v.w));
    *reinterpret_cast<uint2*>(out + i) = o;
}

// ============================================================
// RMSNorm: fp32 in, fp16 out. one block per row of 2048
// ============================================================
__global__ __launch_bounds__(256) void rmsnorm_kernel(
    const float* __restrict__ x, const float* __restrict__ w, __half* __restrict__ o)
{
    const int tid = threadIdx.x;
    const size_t base = (size_t)blockIdx.x * E_;
    float4 v0 = *reinterpret_cast<const float4*>(x + base + tid*4);
    float4 v1 = *reinterpret_cast<const float4*>(x + base + 1024 + tid*4);
    float ss = v0.x*v0.x + v0.y*v0.y + v0.z*v0.z + v0.w*v0.w
             + v1.x*v1.x + v1.y*v1.y + v1.z*v1.z + v1.w*v1.w;
    #pragma unroll
    for (int off = 16; off; off >>= 1) ss += __shfl_xor_sync(0xffffffffu, ss, off);
    __shared__ float sred[8];
    if ((tid & 31) == 0) sred[tid >> 5] = ss;
    __syncthreads();
    float tot = 0.f;
    #pragma unroll
    for (int i = 0; i < 8; i++) tot += sred[i];
    float inv = rsqrtf(tot * (1.0f / (float)E_) + 1e-5f);
    float4 w0 = *reinterpret_cast<const float4*>(w + tid*4);
    float4 w1 = *reinterpret_cast<const float4*>(w + 1024 + tid*4);
    uint2 o0 = make_uint2(packh2(v0.x*inv*w0.x, v0.y*inv*w0.y),
                          packh2(v0.z*inv*w0.z, v0.w*inv*w0.w));
    uint2 o1 = make_uint2(packh2(v1.x*inv*w1.x, v1.y*inv*w1.y),
                          packh2(v1.z*inv*w1.z, v1.w*inv*w1.w));
    *reinterpret_cast<uint2*>(o + base + tid*4)        = o0;
    *reinterpret_cast<uint2*>(o + base + 1024 + tid*4) = o1;
}

// -------- fp16 mma --------
__device__ __forceinline__ void mma_f16(float* c,
    uint32_t a0, uint32_t a1, uint32_t a2, uint32_t a3,
    uint32_t b0, uint32_t b1)
{
    asm volatile(
        "mma.sync.aligned.m16n8k16.row.col.f32.f16.f16.f32 "
        "{%0,%1,%2,%3}, {%4,%5,%6,%7}, {%8,%9}, {%0,%1,%2,%3};"
        : "+f"(c[0]), "+f"(c[1]), "+f"(c[2]), "+f"(c[3])
        : "r"(a0), "r"(a1), "r"(a2), "r"(a3), "r"(b0), "r"(b1));
}

// interleave two uint4 (halves k0..7, k8..15) into perm slot order
// [p0,p4,p1,p5] and [p2,p6,p3,p7]
__device__ __forceinline__ void perm_sts(__half* rowp, uint4 lo, uint4 hi) {
    *reinterpret_cast<uint4*>(rowp)     = make_uint4(lo.x, hi.x, lo.y, hi.y);
    *reinterpret_cast<uint4*>(rowp + 8) = make_uint4(lo.z, hi.z, lo.w, hi.w);
}

// ============================================================
// FP16-in tensor-core GEMM NT: C[M,N] = A[M,K]*B[N,K]^T (+res)
// A,B fp16; C fp32 or fp16 (HOUT). Block 128x128, K-tile 32,
// 256 thr (8 warps 4Mx2N), warp 32x64. Double-buffered.
// ============================================================
template<int HOUT, bool RES>
__global__ __launch_bounds__(256, 2) void hgemm16(
    const __half* __restrict__ A, const __half* __restrict__ B,
    const float* __restrict__ Res, void* __restrict__ Cv,
    int M, int N, int K)
{
    __shared__ __align__(16) __half As[2][2][128][16];
    __shared__ __align__(16) __half Bs[2][2][128][16];

    const int tid  = threadIdx.x;
    const int lane = tid & 31;
    const int warp = tid >> 5;
    const int bm = blockIdx.y * 128;
    const int bn = blockIdx.x * 128;

    const int m0 = (warp & 3) * 32;
    const int n0 = (warp >> 2) * 64;

    // loader: thread -> (row, kk). 128 rows x 2 kk = 256 units.
    const int r_l  = tid >> 1;    // 0..127
    const int kk_l = tid & 1;     // 0..1
    const __half* Ag = A + (size_t)(bm + r_l) * K + kk_l * 16;
    const __half* Bg = B + (size_t)(bn + r_l) * K + kk_l * 16;

    float acc[2][8][4];
    #pragma unroll
    for (int i = 0; i < 2; i++)
        #pragma unroll
        for (int j = 0; j < 8; j++)
            acc[i][j][0] = acc[i][j][1] = acc[i][j][2] = acc[i][j][3] = 0.f;

    // preload tile 0
    {
        uint4 a0 = *reinterpret_cast<const uint4*>(Ag);
        uint4 a1 = *reinterpret_cast<const uint4*>(Ag + 8);
        uint4 b0 = *reinterpret_cast<const uint4*>(Bg);
        uint4 b1 = *reinterpret_cast<const uint4*>(Bg + 8);
        perm_sts(&As[0][kk_l][r_l][0], a0, a1);
        perm_sts(&Bs[0][kk_l][r_l][0], b0, b1);
    }
    __syncthreads();

    const int gr = lane >> 2;
    const int tq = lane & 3;
    const int KT = K >> 5;

    for (int kt = 0; kt < KT; ++kt) {
        const int buf = kt & 1;
        const bool pf = (kt + 1 < KT);
        uint4 pa0, pa1, pb0, pb1;
        if (pf) {
            const __half* Ap = Ag + (size_t)(kt + 1) * 32;
            const __half* Bp = Bg + (size_t)(kt + 1) * 32;
            pa0 = *reinterpret_cast<const uint4*>(Ap);
            pa1 = *reinterpret_cast<const uint4*>(Ap + 8);
            pb0 = *reinterpret_cast<const uint4*>(Bp);
            pb1 = *reinterpret_cast<const uint4*>(Bp + 8);
        }

        #pragma unroll
        for (int kk = 0; kk < 2; ++kk) {
            uint2 ax[2], ay[2];
            #pragma unroll
            for (int mi = 0; mi < 2; mi++) {
                const int r = m0 + mi * 16 + gr;
                ax[mi] = *reinterpret_cast<const uint2*>(&As[buf][kk][r    ][tq * 4]);
                ay[mi] = *reinterpret_cast<const uint2*>(&As[buf][kk][r + 8][tq * 4]);
            }
            #pragma unroll
            for (int ni = 0; ni < 8; ni++) {
                const uint2 bv = *reinterpret_cast<const uint2*>(&Bs[buf][kk][n0 + ni * 8 + gr][tq * 4]);
                #pragma unroll
                for (int mi = 0; mi < 2; mi++)
                    mma_f16(acc[mi][ni], ax[mi].x, ay[mi].x, ax[mi].y, ay[mi].y, bv.x, bv.y);
            }
        }

        if (pf) {
            const int nxt = buf ^ 1;
            perm_sts(&As[nxt][kk_l][r_l][0], pa0, pa1);
            perm_sts(&Bs[nxt][kk_l][r_l][0], pb0, pb1);
            __syncthreads();
        }
    }

    // epilogue
    const int gc = tq * 2;
    #pragma unroll
    for (int mi = 0; mi < 2; mi++) {
        #pragma unroll
        for (int ni = 0; ni < 8; ni++) {
            const int r = bm + m0 + mi * 16 + gr;
            const int c = bn + n0 + ni * 8 + gc;
            float2 lo = make_float2(acc[mi][ni][0], acc[mi][ni][1]);
            float2 hi = make_float2(acc[mi][ni][2], acc[mi][ni][3]);
            if (RES) {
                float2 rlo = *reinterpret_cast<const float2*>(Res + (size_t)r * N + c);
                float2 rhi = *reinterpret_cast<const float2*>(Res + (size_t)(r + 8) * N + c);
                lo.x += rlo.x; lo.y += rlo.y;
                hi.x += rhi.x; hi.y += rhi.y;
            }
            if (HOUT) {
                __half* C = (__half*)Cv;
                *reinterpret_cast<uint32_t*>(C + (size_t)r * N + c)       = packh2(lo.x, lo.y);
                *reinterpret_cast<uint32_t*>(C + (size_t)(r + 8) * N + c) = packh2(hi.x, hi.y);
            } else {
                float* C = (float*)Cv;
                *reinterpret_cast<float2*>(C + (size_t)r * N + c)       = lo;
                *reinterpret_cast<float2*>(C + (size_t)(r + 8) * N + c) = hi;
            }
        }
    }
}

// ============================================================
// RoPE + head reshape, fp16 in/out. q pre-scaled by 0.125.
// ============================================================
__global__ __launch_bounds__(256) void rope_reshape_kernel(
    const __half* __restrict__ qkv, const float* __restrict__ fc,
    __half* __restrict__ qr, __half* __restrict__ kr, __half* __restrict__ vr)
{
    const int gid = blockIdx.x * 256 + threadIdx.x;
    if (gid >= M_ * (QKVN/2)) return;
    const int row = gid / (QKVN/2);
    const int col = (gid - row * (QKVN/2)) * 2;
    const int b = row >> 11;
    const int s = row & (S_-1);
    const float2 xv = unpackh2(*reinterpret_cast<const uint32_t*>(qkv + (size_t)row * QKVN + col));
    const float x0 = xv.x, x1 = xv.y;

    if (col < E_) {
        const int hh = col >> 6, d = col & 63;
        const float c = fc[s*64 + d], sn = fc[s*64 + d + 1];
        *reinterpret_cast<uint32_t*>(qr + ((((size_t)b*H_ + hh) * S_ + s) << 6) + d) =
            packh2((x0*c - x1*sn) * 0.125f, (x1*c + x0*sn) * 0.125f);
    } else if (col < E_ + KV_) {
        const int kc = col - E_;
        const int kh = kc >> 6, d = kc & 63;
        const float c = fc[s*64 + d], sn = fc[s*64 + d + 1];
        *reinterpret_cast<uint32_t*>(kr + ((((size_t)b*KH_ + kh) * S_ + s) << 6) + d) =
            packh2(x0*c - x1*sn, x1*c + x0*sn);
    } else {
        const int vc = col - E_ - KV_;
        const int kh = vc >> 6, d = vc & 63;
        *reinterpret_cast<uint32_t*>(vr + ((((size_t)b*KH_ + kh) * S_ + s) << 6) + d) =
            packh2(x0, x1);
    }
}

// ============================================================
// Flash attention, fp16 mma, causal, GQA 4:1. fp16 output.
// ============================================================
__global__ __launch_bounds__(128) void attn_mma_kernel(
    const __half* __restrict__ qr, const __half* __restrict__ kr,
    const __half* __restrict__ vr, __half* __restrict__ of)
{
    __shared__ __align__(16) __half sQ[4][64][16];
    __shared__ __align__(16) __half sK[4][64][16];
    __shared__ __align__(16) __half sV[64][72];

    const int tid  = threadIdx.x;
    const int lane = tid & 31, warp = tid >> 5;
    const int qt = blockIdx.x, h = blockIdx.y, b = blockIdx.z;
    const int kvh = h >> 2;
    const __half* Q = qr + (((size_t)(b*H_ + h)) * S_ + qt*64) * HD_;
    const __half* K = kr + ((size_t)(b*KH_ + kvh)) * S_ * HD_;
    const __half* V = vr + ((size_t)(b*KH_ + kvh)) * S_ * HD_;

    #pragma unroll
    for (int it = 0; it < 4; it++) {
        const int f = tid + it*128;
        const int r = f >> 3, seg = f & 7;
        const int g = seg >> 1, hp = seg & 1;
        uint4 v4 = *reinterpret_cast<const uint4*>(Q + (size_t)r*64 + seg*8);
        uint32_t* p = reinterpret_cast<uint32_t*>(&sQ[g][r][0]);
        p[hp] = v4.x; p[hp+2] = v4.y; p[hp+4] = v4.z; p[hp+6] = v4.w;
    }

    const int gr = lane >> 2;
    const int tq = lane & 3;
    const int qrow = warp * 16;
    const int lm_r = (lane & 7) + ((lane >> 3) & 1) * 8;
    const int lm_c = ((lane >> 4) & 1) * 8;

    float m0 = -1e30f, m1 = -1e30f, l0 = 0.f, l1 = 0.f;
    float oac[8][4];
    #pragma unroll
    for (int i = 0; i < 8; i++)
        oac[i][0] = oac[i][1] = oac[i][2] = oac[i][3] = 0.f;

    for (int kt = 0; kt <= qt; ++kt) {
        __syncthreads();
        #pragma unroll
        for (int it = 0; it < 4; it++) {
            const int f = tid + it*128;
            const int r = f >> 3, seg = f & 7;
            const int g = seg >> 1, hp = seg & 1;
            uint4 kv4 = *reinterpret_cast<const uint4*>(K + ((size_t)kt*64 + r)*64 + seg*8);
            uint32_t* p = reinterpret_cast<uint32_t*>(&sK[g][r][0]);
            p[hp] = kv4.x; p[hp+2] = kv4.y; p[hp+4] = kv4.z; p[hp+6] = kv4.w;
            uint4 vv4 = *reinterpret_cast<const uint4*>(V + ((size_t)kt*64 + r)*64 + seg*8);
            *reinterpret_cast<uint4*>(&sV[r][seg*8]) = vv4;
        }
        __syncthreads();

        float sc[8][4];
        #pragma unroll
        for (int i = 0; i < 8; i++)
            sc[i][0] = sc[i][1] = sc[i][2] = sc[i][3] = 0.f;
        #pragma unroll
        for (int kk = 0; kk < 4; kk++) {
            const uint2 alo = *reinterpret_cast<const uint2*>(&sQ[kk][qrow + gr    ][tq*4]);
            const uint2 ahi = *reinterpret_cast<const uint2*>(&sQ[kk][qrow + gr + 8][tq*4]);
            #pragma unroll
            for (int ni = 0; ni < 8; ni++) {
                const uint2 bv = *reinterpret_cast<const uint2*>(&sK[kk][ni*8 + gr][tq*4]);
                mma_f16(sc[ni], alo.x, ahi.x, alo.y, ahi.y, bv.x, bv.y);
            }
        }

        if (kt == qt) {
            const int lr0 = qrow + gr, lr1 = lr0 + 8;
            #pragma unroll
            for (int ni = 0; ni < 8; ni++) {
                const int c0 = ni*8 + tq*2, c1 = c0 + 1;
                if (c0 > lr0) sc[ni][0] = -1e30f;
                if (c1 > lr0) sc[ni][1] = -1e30f;
                if (c0 > lr1) sc[ni][2] = -1e30f;
                if (c1 > lr1) sc[ni][3] = -1e30f;
            }
        }

        float mx0 = -1e30f, mx1 = -1e30f;
        #pragma unroll
        for (int ni = 0; ni < 8; ni++) {
            mx0 = fmaxf(mx0, fmaxf(sc[ni][0], sc[ni][1]));
            mx1 = fmaxf(mx1, fmaxf(sc[ni][2], sc[ni][3]));
        }
        mx0 = fmaxf(mx0, __shfl_xor_sync(0xffffffffu, mx0, 1));
        mx0 = fmaxf(mx0, __shfl_xor_sync(0xffffffffu, mx0, 2));
        mx1 = fmaxf(mx1, __shfl_xor_sync(0xffffffffu, mx1, 1));
        mx1 = fmaxf(mx1, __shfl_xor_sync(0xffffffffu, mx1, 2));
        const float nm0 = fmaxf(m0, mx0), nm1 = fmaxf(m1, mx1);
        const float al0 = __expf(m0 - nm0), al1 = __expf(m1 - nm1);
        m0 = nm0; m1 = nm1;

        float s0 = 0.f, s1 = 0.f;
        uint32_t pa[4][4];
        #pragma unroll
        for (int ni = 0; ni < 8; ni++) {
            const float p0 = __expf(sc[ni][0] - nm0);
            const float p1 = __expf(sc[ni][1] - nm0);
            const float p2 = __expf(sc[ni][2] - nm1);
            const float p3 = __expf(sc[ni][3] - nm1);
            s0 += p0 + p1; s1 += p2 + p3;
            const int kk = ni >> 1, w2 = (ni & 1) * 2;
            pa[kk][w2    ] = packh2(p0, p1);
            pa[kk][w2 + 1] = packh2(p2, p3);
        }
        s0 += __shfl_xor_sync(0xffffffffu, s0, 1);
        s0 += __shfl_xor_sync(0xffffffffu, s0, 2);
        s1 += __shfl_xor_sync(0xffffffffu, s1, 1);
        s1 += __shfl_xor_sync(0xffffffffu, s1, 2);
        l0 = l0 * al0 + s0;
        l1 = l1 * al1 + s1;
        #pragma unroll
        for (int ni = 0; ni < 8; ni++) {
            oac[ni][0] *= al0; oac[ni][1] *= al0;
            oac[ni][2] *= al1; oac[ni][3] *= al1;
        }

        #pragma unroll
        for (int kk = 0; kk < 4; kk++) {
            uint32_t bfr[8][2];
            #pragma unroll
            for (int nip = 0; nip < 4; nip++) {
                const uint32_t addr = smem_u32(&sV[16*kk + lm_r][nip*16 + lm_c]);
                asm volatile(
                    "ldmatrix.sync.aligned.m8n8.x4.trans.shared.b16 {%0,%1,%2,%3}, [%4];"
                    : "=r"(bfr[2*nip][0]), "=r"(bfr[2*nip][1]),
                      "=r"(bfr[2*nip+1][0]), "=r"(bfr[2*nip+1][1])
                    : "r"(addr));
            }
            #pragma unroll
            for (int ni = 0; ni < 8; ni++)
                mma_f16(oac[ni], pa[kk][0], pa[kk][1], pa[kk][2], pa[kk][3],
                        bfr[ni][0], bfr[ni][1]);
        }
    }

    const float il0 = 1.0f / l0, il1 = 1.0f / l1;
    const size_t row0 = (size_t)b * S_ + qt*64 + qrow + gr;
    __half* o0 = of + row0 * E_ + h*64;
    __half* o1 = o0 + (size_t)8 * E_;
    #pragma unroll
    for (int ni = 0; ni < 8; ni++) {
        *reinterpret_cast<uint32_t*>(o0 + ni*8 + tq*2) = packh2(oac[ni][0]*il0, oac[ni][1]*il0);
        *reinterpret_cast<uint32_t*>(o1 + ni*8 + tq*2) = packh2(oac[ni][2]*il1, oac[ni][3]*il1);
    }
}

// ============================================================
// SwiGLU fp16: gate = silu(gate) * up (in place)
// ============================================================
__global__ __launch_bounds__(256) void silu_mul_kernel(
    __half* __restrict__ gate, const __half* __restrict__ up)
{
    const size_t i = ((size_t)blockIdx.x * 256 + threadIdx.x) * 4;
    uint2 gu = *reinterpret_cast<uint2*>(gate + i);
    uint2 uu = *reinterpret_cast<const uint2*>(up + i);
    float2 g0 = unpackh2(gu.x), g1 = unpackh2(gu.y);
    float2 u0 = unpackh2(uu.x), u1 = unpackh2(uu.y);
    g0.x = g0.x * u0.x / (1.f + __expf(-g0.x));
    g0.y = g0.y * u0.y / (1.f + __expf(-g0.y));
    g1.x = g1.x * u1.x / (1.f + __expf(-g1.x));
    g1.y = g1.y * u1.y / (1.f + __expf(-g1.y));
    *reinterpret_cast<uint2*>(gate + i) = make_uint2(packh2(g0.x, g0.y), packh2(g1.x, g1.y));
}

// ============================================================
// launch
// ============================================================
extern "C" void kernel_launch(void* const* d_in, const int* in_sizes, int n_in,
                              void* d_out, int out_size)
{
    (void)in_sizes; (void)n_in; (void)out_size;
    const float* x     = (const float*)d_in[0];
    const float* fc    = (const float*)d_in[2];
    const float* w_qkv = (const float*)d_in[3];
    const float* w_o   = (const float*)d_in[4];
    const float* w1    = (const float*)d_in[5];
    const float* w2    = (const float*)d_in[6];
    const float* w3    = (const float*)d_in[7];
    const float* anw   = (const float*)d_in[8];
    const float* fnw   = (const float*)d_in[9];
    float* out = (float*)d_out;

    __half *wqkvh, *woh, *w1h, *w3h, *w2h;
    __half *h, *qkvh, *qh, *kh, *vh, *o, *g, *gate, *up;
    float  *h2;
    cudaGetSymbolAddress((void**)&wqkvh, g_wqkvh);
    cudaGetSymbolAddress((void**)&woh,   g_woh);
    cudaGetSymbolAddress((void**)&w1h,   g_w1h);
    cudaGetSymbolAddress((void**)&w3h,   g_w3h);
    cudaGetSymbolAddress((void**)&w2h,   g_w2h);
    cudaGetSymbolAddress((void**)&h,     g_h);
    cudaGetSymbolAddress((void**)&qkvh,  g_qkvh);
    cudaGetSymbolAddress((void**)&qh,    g_qh);
    cudaGetSymbolAddress((void**)&kh,    g_kh);
    cudaGetSymbolAddress((void**)&vh,    g_vh);
    cudaGetSymbolAddress((void**)&o,     g_o);
    cudaGetSymbolAddress((void**)&h2,    g_h2);
    cudaGetSymbolAddress((void**)&g,     g_g);
    cudaGetSymbolAddress((void**)&gate,  g_gate);
    cudaGetSymbolAddress((void**)&up,    g_up);

    // 0. weight conversion (fp32 -> fp16)
    f2h_kernel<<<(QKVN*E_)/1024, 256>>>(w_qkv, wqkvh);
    f2h_kernel<<<(E_*E_)/1024,   256>>>(w_o,   woh);
    f2h_kernel<<<(F_*E_)/1024,   256>>>(w1,    w1h);
    f2h_kernel<<<(F_*E_)/1024,   256>>>(w3,    w3h);
    f2h_kernel<<<(E_*F_)/1024,   256>>>(w2,    w2h);

    // 1. attn rmsnorm -> fp16
    rmsnorm_kernel<<<M_, 256>>>(x, anw, h);
    // 2. qkv = h @ w_qkv^T -> fp16
    hgemm16<1,false><<<dim3(QKVN/128, M_/128), 256>>>(h, wqkvh, nullptr, qkvh, M_, QKVN, E_);
    // 3. rope + reshape (fp16 -> fp16)
    rope_reshape_kernel<<<(M_*(QKVN/2))/256, 256>>>(qkvh, fc, qh, kh, vh);
    // 4. attention -> fp16 o
    attn_mma_kernel<<<dim3(S_/64, H_, B_), 128>>>(qh, kh, vh, o);
    // 5. h2 = x + o @ w_o^T -> fp32
    hgemm16<0,true><<<dim3(E_/128, M_/128), 256>>>(o, woh, x, h2, M_, E_, E_);
    // 6. ffn rmsnorm -> fp16
    rmsnorm_kernel<<<M_, 256>>>(h2, fnw, g);
    // 7. gate / up projections -> fp16
    hgemm16<1,false><<<dim3(F_/128, M_/128), 256>>>(g, w1h, nullptr, gate, M_, F_, E_);
    hgemm16<1,false><<<dim3(F_/128, M_/128), 256>>>(g, w3h, nullptr, up,   M_, F_, E_);
    // 8. swiglu (fp16)
    silu_mul_kernel<<<((size_t)M_*F_/4)/256, 256>>>(gate, up);
    // 9. out = h2 + act @ w2^T -> fp32
    hgemm16<0,true><<<dim3(E_/128, M_/128), 256>>>(gate, w2h, h2, out, M_, E_, F_);
}